// round 15
// baseline (speedup 1.0000x reference)
#include <cuda_runtime.h>
#include <cuda_fp16.h>
#include <math.h>

#define N_ATOMS 50000
#define HALFN   25024
#define N_EDGES 400000
#define N_MOLS  500
#define HID     128
#define NRBF    20
#define NLAYERS 4
#define NV      (N_ATOMS * HID)

#define TAB_D   1024
#define TAB_MAX 12.0f
#define RBF_STEP (5.0f / (float)(NRBF - 1))

typedef unsigned long long ull;
typedef unsigned int uint;

// ---------------- device scratch (double-buffered state) ----------------
__device__ float  g_s0[NV], g_s1[NV];
__device__ __half g_sh0[NV], g_sh1[NV];
__device__ __half g_vh0[3 * NV], g_vh1[3 * NV];
__device__ __half g_ms[NV];
__device__ __half g_vn[NV];
__device__ __half g_mvh[3 * NV];
__device__ __half2 g_htabh[NLAYERS * TAB_D * 3 * HID];
__device__ float g_hmol[N_MOLS * HID];
__device__ float g_cnt[N_MOLS];

// CSR scratch
__device__ int   g_deg[N_ATOMS];
__device__ int   g_rowptr[N_ATOMS + 1];
__device__ int   g_cursor[N_ATOMS];
__device__ int   g_bsum[128];
__device__ int   g_ecol[N_EDGES];
__device__ float4 g_egeo[N_EDGES];

__device__ __forceinline__ float silu_f(float x) { return x / (1.0f + expf(-x)); }

__device__ __forceinline__ uint f2tf32(float x) {
    uint r;
    asm("cvt.rna.tf32.f32 %0, %1;" : "=r"(r) : "f"(x));
    return r;
}
__device__ __forceinline__ float tf32f(float x) { return __uint_as_float(f2tf32(x)); }

__device__ __forceinline__ void mma_tf32(float* c, uint a0, uint a1, uint a2, uint a3,
                                         uint b0, uint b1) {
    asm("mma.sync.aligned.m16n8k8.row.col.f32.tf32.tf32.f32 "
        "{%0,%1,%2,%3},{%4,%5,%6,%7},{%8,%9},{%0,%1,%2,%3};"
        : "+f"(c[0]), "+f"(c[1]), "+f"(c[2]), "+f"(c[3])
        : "r"(a0), "r"(a1), "r"(a2), "r"(a3), "r"(b0), "r"(b1));
}

__device__ __forceinline__ float4 h4_to_f4(uint2 u) {
    __half2 h01 = *(__half2*)&u.x;
    __half2 h23 = *(__half2*)&u.y;
    float2 a = __half22float2(h01);
    float2 b = __half22float2(h23);
    return make_float4(a.x, a.y, b.x, b.y);
}
__device__ __forceinline__ uint2 f4_to_h4(float x, float y, float z, float w) {
    __half2 h01 = __floats2half2_rn(x, y);
    __half2 h23 = __floats2half2_rn(z, w);
    uint2 r;
    r.x = *(unsigned*)&h01;
    r.y = *(unsigned*)&h23;
    return r;
}

// ---------------- init ----------------
__global__ void init_kernel(const int* __restrict__ z, const float* __restrict__ emb) {
    int idx = blockIdx.x * blockDim.x + threadIdx.x;
    if (idx < N_ATOMS) g_deg[idx] = 0;
    if (idx < N_MOLS * HID) g_hmol[idx] = 0.f;
    if (idx < N_MOLS) g_cnt[idx] = 0.f;
    if (idx >= NV) return;
    int n = idx >> 7;
    int j = idx & 127;
    float s = emb[z[n] * HID + j];
    g_s0[idx] = s;
    g_sh0[idx] = __float2half(s);
}

// ---------------- CSR build ----------------
__global__ void hist_kernel(const int* __restrict__ ei) {
    int e = blockIdx.x * blockDim.x + threadIdx.x;
    if (e >= N_EDGES) return;
    atomicAdd(&g_deg[ei[e]], 1);
}

#define SCAN_B 512
__global__ void scan1_kernel() {
    __shared__ int s[SCAN_B];
    int t = threadIdx.x;
    int i = blockIdx.x * SCAN_B + t;
    int v = (i < N_ATOMS) ? g_deg[i] : 0;
    s[t] = v;
    __syncthreads();
    for (int off = 1; off < SCAN_B; off <<= 1) {
        int add = (t >= off) ? s[t - off] : 0;
        __syncthreads();
        s[t] += add;
        __syncthreads();
    }
    if (i < N_ATOMS) g_rowptr[i] = s[t] - v;
    if (t == SCAN_B - 1) g_bsum[blockIdx.x] = s[t];
}

__global__ void scan2_kernel(int nblocks) {
    __shared__ int s[128];
    int t = threadIdx.x;
    int v = (t < nblocks) ? g_bsum[t] : 0;
    s[t] = v;
    __syncthreads();
    for (int off = 1; off < 128; off <<= 1) {
        int add = (t >= off) ? s[t - off] : 0;
        __syncthreads();
        s[t] += add;
        __syncthreads();
    }
    if (t < nblocks) g_bsum[t] = s[t] - v;
}

__global__ void scan3_kernel() {
    int i = blockIdx.x * blockDim.x + threadIdx.x;
    if (i < N_ATOMS) {
        int rp = g_rowptr[i] + g_bsum[i >> 9];
        g_rowptr[i] = rp;
        g_cursor[i] = rp;
    }
    if (i == 0) g_rowptr[N_ATOMS] = N_EDGES;
}

__global__ void scatter_kernel(const int* __restrict__ ei, const float* __restrict__ pos) {
    int e = blockIdx.x * blockDim.x + threadIdx.x;
    if (e >= N_EDGES) return;
    int r = ei[e];
    int c = ei[N_EDGES + e];
    float dx = pos[c * 3 + 0] - pos[r * 3 + 0];
    float dy = pos[c * 3 + 1] - pos[r * 3 + 1];
    float dz = pos[c * 3 + 2] - pos[r * 3 + 2];
    float dist = sqrtf(dx * dx + dy * dy + dz * dz);
    float inv = 1.0f / (dist + 1e-8f);
    const float INV_DELTA = (float)(TAB_D - 1) / TAB_MAX;
    int p = atomicAdd(&g_cursor[r], 1);
    g_ecol[p] = c;
    g_egeo[p] = make_float4(dx * inv, dy * inv, dz * inv, dist * INV_DELTA);
}

// ---------------- filter table build ----------------
#define TAB_SMEM_FLOATS 20736

extern "C" __global__ void __launch_bounds__(512, 1)
table_kernel(const float* __restrict__ fW1, const float* __restrict__ fb1,
             const float* __restrict__ fW2, const float* __restrict__ fb2) {
    extern __shared__ float sm[];
    float* hid = sm;
    float* rbf_s = sm + 8448;
    float* w1_s = sm + 9728;
    float* w2_s = sm + 8448;

    const int tid = threadIdx.x;
    const int layer = blockIdx.y;
    const int g0 = blockIdx.x * 64;
    const float* W1 = fW1 + layer * NRBF * HID;
    const float* b1 = fb1 + layer * HID;
    const float* W2 = fW2 + layer * HID * 3 * HID;
    const float* b2 = fb2 + layer * 3 * HID;
    const float DELTA = TAB_MAX / (float)(TAB_D - 1);

    for (int idx = tid; idx < 64 * NRBF; idx += 512) {
        int e = idx / NRBF, k = idx % NRBF;
        float d = (float)(g0 + e) * DELTA - RBF_STEP * (float)k;
        rbf_s[idx] = expf(-d * d);
    }
    for (int idx = tid; idx < NRBF * HID; idx += 512) w1_s[idx] = W1[idx];
    __syncthreads();

    const int jg = tid & 31;
    const int eg = tid >> 5;
    const int j0 = jg * 4;
    const int el0 = eg * 4;

    float hacc[4][4];
#pragma unroll
    for (int a = 0; a < 4; a++)
#pragma unroll
        for (int b = 0; b < 4; b++) hacc[a][b] = b1[j0 + b];
#pragma unroll
    for (int k = 0; k < NRBF; k++) {
        float r[4];
#pragma unroll
        for (int a = 0; a < 4; a++) r[a] = rbf_s[(el0 + a) * NRBF + k];
        float4 w = *(const float4*)&w1_s[k * HID + j0];
        float wv[4] = {w.x, w.y, w.z, w.w};
#pragma unroll
        for (int a = 0; a < 4; a++)
#pragma unroll
            for (int b = 0; b < 4; b++) hacc[a][b] += r[a] * wv[b];
    }
#pragma unroll
    for (int a = 0; a < 4; a++)
#pragma unroll
        for (int b = 0; b < 4; b++) hid[(el0 + a) * 132 + j0 + b] = silu_f(hacc[a][b]);
    __syncthreads();

    float a_ss[4][4], a_vv[4][4], a_sv[4][4];
#pragma unroll
    for (int a = 0; a < 4; a++)
#pragma unroll
        for (int b = 0; b < 4; b++) { a_ss[a][b] = 0.f; a_vv[a][b] = 0.f; a_sv[a][b] = 0.f; }

    for (int kc = 0; kc < HID; kc += 32) {
        __syncthreads();
        for (int idx = tid; idx < 32 * 384; idx += 512) w2_s[idx] = W2[kc * 384 + idx];
        __syncthreads();
#pragma unroll 8
        for (int kk = 0; kk < 32; kk++) {
            float h[4];
#pragma unroll
            for (int a = 0; a < 4; a++) h[a] = hid[(el0 + a) * 132 + kc + kk];
            float4 wss = *(const float4*)&w2_s[kk * 384 + j0];
            float4 wvv = *(const float4*)&w2_s[kk * 384 + 128 + j0];
            float4 wsv = *(const float4*)&w2_s[kk * 384 + 256 + j0];
            float ss[4] = {wss.x, wss.y, wss.z, wss.w};
            float vv[4] = {wvv.x, wvv.y, wvv.z, wvv.w};
            float sv[4] = {wsv.x, wsv.y, wsv.z, wsv.w};
#pragma unroll
            for (int a = 0; a < 4; a++)
#pragma unroll
                for (int b = 0; b < 4; b++) {
                    a_ss[a][b] += h[a] * ss[b];
                    a_vv[a][b] += h[a] * vv[b];
                    a_sv[a][b] += h[a] * sv[b];
                }
        }
    }

#pragma unroll
    for (int a = 0; a < 4; a++) {
        int gi = g0 + el0 + a;
        __half* Tx = (__half*)(g_htabh + ((size_t)layer * TAB_D + gi) * 384);
        __half* Ty = (__half*)(g_htabh + ((size_t)layer * TAB_D + gi - 1) * 384);
#pragma unroll
        for (int b = 0; b < 4; b++) {
            int ch = j0 + b;
            float hss = a_ss[a][b] + b2[ch];
            float hvv = a_vv[a][b] + b2[128 + ch];
            float hsv = a_sv[a][b] + b2[256 + ch];
            Tx[(0 * 128 + ch) * 2] = __float2half(hss);
            Tx[(1 * 128 + ch) * 2] = __float2half(hvv);
            Tx[(2 * 128 + ch) * 2] = __float2half(hsv);
            if (gi > 0) {
                Ty[(0 * 128 + ch) * 2 + 1] = __float2half(hss);
                Ty[(1 * 128 + ch) * 2 + 1] = __float2half(hvv);
                Ty[(2 * 128 + ch) * 2 + 1] = __float2half(hsv);
            }
        }
    }
}

// ---------------- edge message kernel (row range + parity buffers) ----------------
extern "C" __global__ void __launch_bounds__(256)
msg_kernel(int layer, int row0, int rowN) {
    int r = row0 + ((blockIdx.x * 256 + threadIdx.x) >> 5);
    int lane = threadIdx.x & 31;
    if (r >= rowN) return;

    const __half* sh_in = (layer & 1) ? g_sh1 : g_sh0;
    const __half* vh_in = (layer & 1) ? g_vh1 : g_vh0;

    int beg = g_rowptr[r];
    int end = g_rowptr[r + 1];
    int base = r * HID + lane * 4;

    if (beg >= end) {
        uint2 z; z.x = 0u; z.y = 0u;
        *(uint2*)&g_ms[base] = z;
        *(uint2*)&g_vn[base] = z;
        *(uint2*)&g_mvh[0 * NV + base] = z;
        *(uint2*)&g_mvh[1 * NV + base] = z;
        *(uint2*)&g_mvh[2 * NV + base] = z;
        return;
    }

    const bool hasv = (layer != 0);
    const __half2* Tl = g_htabh + (size_t)layer * TAB_D * 384;

    float accS[4] = {0.f, 0.f, 0.f, 0.f};
    float accV[12];
#pragma unroll
    for (int q = 0; q < 12; q++) accV[q] = 0.f;

    int colN = __ldg(&g_ecol[beg]);
    float4 geoN = __ldg(&g_egeo[beg]);
    float fN;
    const uint4* TbN;
    {
        float u = geoN.w;
        int i0 = (int)u;
        if (i0 > TAB_D - 2) i0 = TAB_D - 2;
        fN = fminf(u - (float)i0, 1.0f);
        TbN = (const uint4*)(Tl + (size_t)i0 * 384);
    }
    uint4 t0N = __ldg(&TbN[lane]);
    uint4 t1N = __ldg(&TbN[32 + lane]);
    uint4 t2N = __ldg(&TbN[64 + lane]);
    uint2 sN = __ldcg((const uint2*)&sh_in[colN * HID + lane * 4]);
    uint2 v0N, v1N, v2N;
    v0N.x = v0N.y = v1N.x = v1N.y = v2N.x = v2N.y = 0u;
    if (hasv) {
        v0N = __ldcg((const uint2*)&vh_in[0 * NV + colN * HID + lane * 4]);
        v1N = __ldcg((const uint2*)&vh_in[1 * NV + colN * HID + lane * 4]);
        v2N = __ldcg((const uint2*)&vh_in[2 * NV + colN * HID + lane * 4]);
    }

    for (int p = beg; p < end; p++) {
        float4 geo = geoN;
        float f = fN;
        uint4 t0 = t0N, t1 = t1N, t2 = t2N;
        uint2 sv = sN, v0 = v0N, v1 = v1N, v2 = v2N;

        if (p + 1 < end) {
            int colX = __ldg(&g_ecol[p + 1]);
            geoN = __ldg(&g_egeo[p + 1]);
            float u = geoN.w;
            int i0 = (int)u;
            if (i0 > TAB_D - 2) i0 = TAB_D - 2;
            fN = fminf(u - (float)i0, 1.0f);
            TbN = (const uint4*)(Tl + (size_t)i0 * 384);
            t0N = __ldg(&TbN[lane]);
            t1N = __ldg(&TbN[32 + lane]);
            t2N = __ldg(&TbN[64 + lane]);
            sN = __ldcg((const uint2*)&sh_in[colX * HID + lane * 4]);
            if (hasv) {
                v0N = __ldcg((const uint2*)&vh_in[0 * NV + colX * HID + lane * 4]);
                v1N = __ldcg((const uint2*)&vh_in[1 * NV + colX * HID + lane * 4]);
                v2N = __ldcg((const uint2*)&vh_in[2 * NV + colX * HID + lane * 4]);
            }
        }

        float4 scf = h4_to_f4(sv);
        float sc[4] = {scf.x, scf.y, scf.z, scf.w};
        float vc0[4], vc1[4], vc2[4];
        if (hasv) {
            float4 a0 = h4_to_f4(v0);
            float4 a1 = h4_to_f4(v1);
            float4 a2 = h4_to_f4(v2);
            vc0[0] = a0.x; vc0[1] = a0.y; vc0[2] = a0.z; vc0[3] = a0.w;
            vc1[0] = a1.x; vc1[1] = a1.y; vc1[2] = a1.z; vc1[3] = a1.w;
            vc2[0] = a2.x; vc2[1] = a2.y; vc2[2] = a2.z; vc2[3] = a2.w;
        }

        const __half2* e0 = (const __half2*)&t0;
        const __half2* e1 = (const __half2*)&t1;
        const __half2* e2 = (const __half2*)&t2;
#pragma unroll
        for (int c = 0; c < 4; c++) {
            float2 pss = __half22float2(e0[c]);
            float2 pvv = __half22float2(e1[c]);
            float2 psv = __half22float2(e2[c]);
            float hss = pss.x + f * (pss.y - pss.x);
            float hvv = pvv.x + f * (pvv.y - pvv.x);
            float hsv = psv.x + f * (psv.y - psv.x);
            accS[c] += hss * sc[c];
            float cc = hsv * sc[c];
            if (hasv) {
                accV[c]     += hvv * vc0[c] + cc * geo.x;
                accV[4 + c] += hvv * vc1[c] + cc * geo.y;
                accV[8 + c] += hvv * vc2[c] + cc * geo.z;
            } else {
                accV[c]     += cc * geo.x;
                accV[4 + c] += cc * geo.y;
                accV[8 + c] += cc * geo.z;
            }
        }
    }

    *(uint2*)&g_ms[base] = f4_to_h4(accS[0], accS[1], accS[2], accS[3]);
    float vn[4];
#pragma unroll
    for (int c = 0; c < 4; c++)
        vn[c] = sqrtf(accV[c] * accV[c] + accV[4 + c] * accV[4 + c] + accV[8 + c] * accV[8 + c]);
    *(uint2*)&g_vn[base] = f4_to_h4(vn[0], vn[1], vn[2], vn[3]);
    *(uint2*)&g_mvh[0 * NV + base] = f4_to_h4(accV[0], accV[1], accV[2], accV[3]);
    *(uint2*)&g_mvh[1 * NV + base] = f4_to_h4(accV[4], accV[5], accV[6], accV[7]);
    *(uint2*)&g_mvh[2 * NV + base] = f4_to_h4(accV[8], accV[9], accV[10], accV[11]);
}

// ---------------- node update kernel (tf32 mma.sync; parity buffers) ----------------
#define NT 64
#define XS_STRIDE 76
#define WC_STRIDE 132
#define NODE_SMEM_FLOATS 23040

extern "C" __global__ void __launch_bounds__(256, 2)
node_kernel(int layer, int n0base,
            const float* __restrict__ uW1, const float* __restrict__ ub1,
            const float* __restrict__ uW2, const float* __restrict__ ub2) {
    extern __shared__ float sm[];
    float* xs_t = sm;
    float* wc   = sm + 4864;
    float* ts_t = sm + 13312;
    __half* alpha_s = (__half*)sm;

    const float* s_in  = (layer & 1) ? g_s1 : g_s0;
    float*       s_out = (layer & 1) ? g_s0 : g_s1;
    __half*      sh_out = (layer & 1) ? g_sh0 : g_sh1;
    const __half* vh_in = (layer & 1) ? g_vh1 : g_vh0;
    __half*      vh_out = (layer & 1) ? g_vh0 : g_vh1;

    const int tid = threadIdx.x;
    const int n0 = n0base + blockIdx.x * NT;
    const float* W1 = uW1 + layer * 384 * HID;
    const float* b1 = ub1 + layer * HID;
    const float* W2 = uW2 + layer * HID * 384;
    const float* b2 = ub2 + layer * 384;

    const int w = tid >> 5;
    const int lane = tid & 31;
    const int gid = lane >> 2;
    const int tig = lane & 3;
    const int wn2 = w >> 2;
    const int wcq = w & 3;
    const int nbase = 32 * wn2 + gid;
    const int cbase = 32 * wcq + gid;

    const int snode = tid & 63;
    const int sq = (tid >> 6) << 2;
    const int sgn = n0 + snode;
    const bool svalid = (sgn < N_ATOMS);

    float4 wreg[8];
#pragma unroll
    for (int q = 0; q < 8; q++) {
        int idx = q * 256 + tid;
        int k = idx >> 5, c4 = idx & 31;
        wreg[q] = *(const float4*)&W1[k * HID + c4 * 4];
    }

    float4 xpre[4];
    {
        const float* sp = s_in + (size_t)sgn * HID;
#pragma unroll
        for (int q = 0; q < 4; q++)
            xpre[q] = svalid ? *(const float4*)&sp[sq + 16 * q]
                             : make_float4(0.f, 0.f, 0.f, 0.f);
    }

    // ---- stage 1: T = silu(X @ W1 + b1) ----
    float c1r[2][4][4];
#pragma unroll
    for (int nt = 0; nt < 4; nt++) {
        int cl = 32 * wcq + 8 * nt + 2 * tig;
        float bb0 = b1[cl], bb1 = b1[cl + 1];
#pragma unroll
        for (int mt = 0; mt < 2; mt++) {
            c1r[mt][nt][0] = bb0; c1r[mt][nt][1] = bb1;
            c1r[mt][nt][2] = bb0; c1r[mt][nt][3] = bb1;
        }
    }

    for (int kc = 0; kc < 384; kc += 64) {
        __syncthreads();
#pragma unroll
        for (int q = 0; q < 8; q++) {
            int idx = q * 256 + tid;
            int k = idx >> 5, c4 = idx & 31;
            *(float4*)&wc[k * WC_STRIDE + c4 * 4] =
                make_float4(tf32f(wreg[q].x), tf32f(wreg[q].y),
                            tf32f(wreg[q].z), tf32f(wreg[q].w));
        }
#pragma unroll
        for (int q = 0; q < 4; q++) {
            int kl = sq + 16 * q;
            xs_t[(kl + 0) * XS_STRIDE + snode] = tf32f(xpre[q].x);
            xs_t[(kl + 1) * XS_STRIDE + snode] = tf32f(xpre[q].y);
            xs_t[(kl + 2) * XS_STRIDE + snode] = tf32f(xpre[q].z);
            xs_t[(kl + 3) * XS_STRIDE + snode] = tf32f(xpre[q].w);
        }
        __syncthreads();
        if (kc + 64 < 384) {
            int nkc = kc + 64;
#pragma unroll
            for (int q = 0; q < 8; q++) {
                int idx = q * 256 + tid;
                int k = idx >> 5, c4 = idx & 31;
                wreg[q] = *(const float4*)&W1[(nkc + k) * HID + c4 * 4];
            }
            if (nkc < 128) {
                const float* sp = s_in + (size_t)sgn * HID + nkc;
#pragma unroll
                for (int q = 0; q < 4; q++)
                    xpre[q] = svalid ? *(const float4*)&sp[sq + 16 * q]
                                     : make_float4(0.f, 0.f, 0.f, 0.f);
            } else {
                const __half* hp = ((nkc < 256) ? g_ms : g_vn) + (size_t)sgn * HID + (nkc & 127);
#pragma unroll
                for (int q = 0; q < 4; q++)
                    xpre[q] = svalid ? h4_to_f4(*(const uint2*)&hp[sq + 16 * q])
                                     : make_float4(0.f, 0.f, 0.f, 0.f);
            }
        } else {
#pragma unroll
            for (int q = 0; q < 8; q++) {
                int idx = q * 256 + tid;
                int k = idx >> 5, c4 = idx & 31;
                wreg[q] = *(const float4*)&W2[k * 384 + c4 * 4];
            }
        }
#pragma unroll
        for (int kk8 = 0; kk8 < 8; kk8++) {
            int kb = kk8 * 8;
            const float* xr0 = &xs_t[(kb + tig) * XS_STRIDE];
            const float* xr1 = &xs_t[(kb + tig + 4) * XS_STRIDE];
            uint a[2][4];
#pragma unroll
            for (int mt = 0; mt < 2; mt++) {
                int nb = nbase + 16 * mt;
                a[mt][0] = __float_as_uint(xr0[nb]);
                a[mt][1] = __float_as_uint(xr0[nb + 8]);
                a[mt][2] = __float_as_uint(xr1[nb]);
                a[mt][3] = __float_as_uint(xr1[nb + 8]);
            }
            const float* wr0 = &wc[(kb + tig) * WC_STRIDE];
            const float* wr1 = &wc[(kb + tig + 4) * WC_STRIDE];
#pragma unroll
            for (int nt = 0; nt < 4; nt++) {
                uint b0 = __float_as_uint(wr0[cbase + 8 * nt]);
                uint b1u = __float_as_uint(wr1[cbase + 8 * nt]);
                mma_tf32(c1r[0][nt], a[0][0], a[0][1], a[0][2], a[0][3], b0, b1u);
                mma_tf32(c1r[1][nt], a[1][0], a[1][1], a[1][2], a[1][3], b0, b1u);
            }
        }
    }

#pragma unroll
    for (int mt = 0; mt < 2; mt++) {
        int lr = 32 * wn2 + 16 * mt + gid;
#pragma unroll
        for (int nt = 0; nt < 4; nt++) {
            int cl = 32 * wcq + 8 * nt + 2 * tig;
            ts_t[(cl + 0) * XS_STRIDE + lr]     = tf32f(silu_f(c1r[mt][nt][0]));
            ts_t[(cl + 1) * XS_STRIDE + lr]     = tf32f(silu_f(c1r[mt][nt][1]));
            ts_t[(cl + 0) * XS_STRIDE + lr + 8] = tf32f(silu_f(c1r[mt][nt][2]));
            ts_t[(cl + 1) * XS_STRIDE + lr + 8] = tf32f(silu_f(c1r[mt][nt][3]));
        }
    }

    // ---- stage 2: U = T @ W2 + b2 ----
    float u2r[2][4][4];
    for (int c = 0; c < 6; c++) {
        int jb = c >> 1;
        int kc2 = (c & 1) * 64;
        if (kc2 == 0) {
#pragma unroll
            for (int mt = 0; mt < 2; mt++)
#pragma unroll
                for (int nt = 0; nt < 4; nt++)
#pragma unroll
                    for (int x = 0; x < 4; x++) u2r[mt][nt][x] = 0.f;
        }
        __syncthreads();
#pragma unroll
        for (int q = 0; q < 8; q++) {
            int idx = q * 256 + tid;
            int k = idx >> 5, c4 = idx & 31;
            *(float4*)&wc[k * WC_STRIDE + c4 * 4] =
                make_float4(tf32f(wreg[q].x), tf32f(wreg[q].y),
                            tf32f(wreg[q].z), tf32f(wreg[q].w));
        }
        __syncthreads();
        if (c < 5) {
            int cn = c + 1;
            int jbn = cn >> 1;
            int kc2n = (cn & 1) * 64;
#pragma unroll
            for (int q = 0; q < 8; q++) {
                int idx = q * 256 + tid;
                int k = idx >> 5, c4 = idx & 31;
                wreg[q] = *(const float4*)&W2[(kc2n + k) * 384 + jbn * 128 + c4 * 4];
            }
        }
#pragma unroll
        for (int kk8 = 0; kk8 < 8; kk8++) {
            int kb = kk8 * 8;
            const float* tr0 = &ts_t[(kc2 + kb + tig) * XS_STRIDE];
            const float* tr1 = &ts_t[(kc2 + kb + tig + 4) * XS_STRIDE];
            uint a[2][4];
#pragma unroll
            for (int mt = 0; mt < 2; mt++) {
                int nb = nbase + 16 * mt;
                a[mt][0] = __float_as_uint(tr0[nb]);
                a[mt][1] = __float_as_uint(tr0[nb + 8]);
                a[mt][2] = __float_as_uint(tr1[nb]);
                a[mt][3] = __float_as_uint(tr1[nb + 8]);
            }
            const float* wr0 = &wc[(kb + tig) * WC_STRIDE];
            const float* wr1 = &wc[(kb + tig + 4) * WC_STRIDE];
#pragma unroll
            for (int nt = 0; nt < 4; nt++) {
                uint b0 = __float_as_uint(wr0[cbase + 8 * nt]);
                uint b1u = __float_as_uint(wr1[cbase + 8 * nt]);
                mma_tf32(u2r[0][nt], a[0][0], a[0][1], a[0][2], a[0][3], b0, b1u);
                mma_tf32(u2r[1][nt], a[1][0], a[1][1], a[1][2], a[1][3], b0, b1u);
            }
        }

        if (kc2 == 64) {
#pragma unroll
            for (int mt = 0; mt < 2; mt++) {
#pragma unroll
                for (int rs = 0; rs < 2; rs++) {
                    int lr = 32 * wn2 + 16 * mt + gid + rs * 8;
                    int gn = n0 + lr;
                    if (gn >= N_ATOMS) continue;
#pragma unroll
                    for (int nt = 0; nt < 4; nt++) {
                        int j = 32 * wcq + 8 * nt + 2 * tig;
                        float u0 = u2r[mt][nt][rs * 2 + 0] + b2[jb * 128 + j];
                        float u1 = u2r[mt][nt][rs * 2 + 1] + b2[jb * 128 + j + 1];
                        if (jb == 0) {
                            float2 s = *(const float2*)&s_in[gn * HID + j];
                            s.x += u0; s.y += u1;
                            *(float2*)&s_out[gn * HID + j] = s;
                            *(__half2*)&sh_out[gn * HID + j] = __floats2half2_rn(s.x, s.y);
                        } else if (jb == 1) {
                            *(__half2*)&alpha_s[lr * HID + j] = __floats2half2_rn(u0, u1);
                        } else {
                            float2 al = __half22float2(*(__half2*)&alpha_s[lr * HID + j]);
#pragma unroll
                            for (int d = 0; d < 3; d++) {
                                float2 mv = __half22float2(*(__half2*)&g_mvh[d * NV + gn * HID + j]);
                                float2 vo = make_float2(0.f, 0.f);
                                if (layer != 0)
                                    vo = __half22float2(*(const __half2*)&vh_in[d * NV + gn * HID + j]);
                                float nx = al.x * vo.x + u0 * mv.x;
                                float ny = al.y * vo.y + u1 * mv.y;
                                *(__half2*)&vh_out[d * NV + gn * HID + j] = __floats2half2_rn(nx, ny);
                            }
                        }
                    }
                }
            }
        }
    }
}

// ---------------- molecule pooling + heads ----------------
__global__ void pool_acc_kernel(const int* __restrict__ batch) {
    int idx = blockIdx.x * blockDim.x + threadIdx.x;
    if (idx >= NV) return;
    int n = idx >> 7;
    int j = idx & 127;
    int m = batch[n];
    atomicAdd(&g_hmol[m * HID + j], g_s0[idx]);   // final parity after 4 layers: buffer 0
    if (j == 0) atomicAdd(&g_cnt[m], 1.0f);
}

__global__ void head_kernel(const float* __restrict__ lW1, const float* __restrict__ lb1,
                            const float* __restrict__ lW2, const float* __restrict__ lb2,
                            const float* __restrict__ pW1, const float* __restrict__ pb1,
                            const float* __restrict__ pW2, const float* __restrict__ pb2,
                            float* __restrict__ out) {
    __shared__ float hm[HID];
    __shared__ float tt[HID];
    __shared__ float red[HID];
    int m = blockIdx.x;
    int j = threadIdx.x;
    float cnt = g_cnt[m];
    hm[j] = g_hmol[m * HID + j] / cnt;
    __syncthreads();

    float acc = lb1[j];
    for (int k = 0; k < HID; k++) acc += hm[k] * lW1[k * HID + j];
    tt[j] = silu_f(acc);
    __syncthreads();
    red[j] = tt[j] * lW2[j];
    __syncthreads();
    for (int s = 64; s > 0; s >>= 1) {
        if (j < s) red[j] += red[j + s];
        __syncthreads();
    }
    if (j == 0) out[m] = red[0] + lb2[0];
    __syncthreads();

    acc = pb1[j];
    for (int k = 0; k < HID; k++) acc += hm[k] * pW1[k * HID + j];
    tt[j] = silu_f(acc);
    __syncthreads();
    red[j] = tt[j] * pW2[j];
    __syncthreads();
    for (int s = 64; s > 0; s >>= 1) {
        if (j < s) red[j] += red[j + s];
        __syncthreads();
    }
    if (j == 0) {
        float x = red[0] + pb2[0];
        out[N_MOLS + m] = 1.0f / (1.0f + expf(-x));
    }
}

// ---------------- streams/events (created once at load) ----------------
struct GpuSync {
    cudaStream_t s2;
    cudaEvent_t ev[2 * NLAYERS];
    GpuSync() {
        cudaStreamCreateWithFlags(&s2, cudaStreamNonBlocking);
        for (int i = 0; i < 2 * NLAYERS; i++)
            cudaEventCreateWithFlags(&ev[i], cudaEventDisableTiming);
    }
};
static GpuSync g_sync;

// ---------------- launch ----------------
extern "C" void kernel_launch(void* const* d_in, const int* in_sizes, int n_in,
                              void* d_out, int out_size) {
    const int* z = (const int*)d_in[0];
    const float* pos = (const float*)d_in[1];
    const int* ei = (const int*)d_in[2];
    const int* batch = (const int*)d_in[3];
    const float* emb = (const float*)d_in[4];
    const float* fW1 = (const float*)d_in[5];
    const float* fb1 = (const float*)d_in[6];
    const float* fW2 = (const float*)d_in[7];
    const float* fb2 = (const float*)d_in[8];
    const float* uW1 = (const float*)d_in[9];
    const float* ub1 = (const float*)d_in[10];
    const float* uW2 = (const float*)d_in[11];
    const float* ub2 = (const float*)d_in[12];
    const float* lW1 = (const float*)d_in[13];
    const float* lb1 = (const float*)d_in[14];
    const float* lW2 = (const float*)d_in[15];
    const float* lb2 = (const float*)d_in[16];
    const float* pW1 = (const float*)d_in[17];
    const float* pb1 = (const float*)d_in[18];
    const float* pW2 = (const float*)d_in[19];
    const float* pb2 = (const float*)d_in[20];
    float* out = (float*)d_out;

    cudaFuncSetAttribute(table_kernel, cudaFuncAttributeMaxDynamicSharedMemorySize,
                         TAB_SMEM_FLOATS * 4);
    cudaFuncSetAttribute(node_kernel, cudaFuncAttributeMaxDynamicSharedMemorySize,
                         NODE_SMEM_FLOATS * 4);

    init_kernel<<<(NV + 255) / 256, 256>>>(z, emb);

    const int scan_blocks = (N_ATOMS + SCAN_B - 1) / SCAN_B;
    hist_kernel<<<(N_EDGES + 255) / 256, 256>>>(ei);
    scan1_kernel<<<scan_blocks, SCAN_B>>>();
    scan2_kernel<<<1, 128>>>(scan_blocks);
    scan3_kernel<<<(N_ATOMS + 255) / 256, 256>>>();
    scatter_kernel<<<(N_EDGES + 255) / 256, 256>>>(ei, pos);

    table_kernel<<<dim3(TAB_D / 64, NLAYERS), 512, TAB_SMEM_FLOATS * 4>>>(fW1, fb1, fW2, fb2);

    const int msgA_blocks = HALFN / 8;                            // 3128
    const int msgB_blocks = (N_ATOMS - HALFN + 7) / 8;            // 3122
    const int nodeA_blocks = HALFN / NT;                          // 391
    const int nodeB_blocks = (N_ATOMS - HALFN + NT - 1) / NT;     // 391

    for (int layer = 0; layer < NLAYERS; layer++) {
        // msgA at full machine
        msg_kernel<<<msgA_blocks, 256>>>(layer, 0, HALFN);
        cudaEventRecord(g_sync.ev[2 * layer], 0);
        cudaStreamWaitEvent(g_sync.s2, g_sync.ev[2 * layer], 0);
        // msgB (stream s2)  ||  nodeA (stream 0)
        msg_kernel<<<msgB_blocks, 256, 0, g_sync.s2>>>(layer, HALFN, N_ATOMS);
        node_kernel<<<nodeA_blocks, 256, NODE_SMEM_FLOATS * 4>>>(layer, 0, uW1, ub1, uW2, ub2);
        cudaEventRecord(g_sync.ev[2 * layer + 1], g_sync.s2);
        cudaStreamWaitEvent(0, g_sync.ev[2 * layer + 1], 0);
        // nodeB
        node_kernel<<<nodeB_blocks, 256, NODE_SMEM_FLOATS * 4>>>(layer, HALFN, uW1, ub1, uW2, ub2);
    }

    pool_acc_kernel<<<(NV + 255) / 256, 256>>>(batch);
    head_kernel<<<N_MOLS, HID>>>(lW1, lb1, lW2, lb2, pW1, pb1, pW2, pb2, out);
}

// round 16
// speedup vs baseline: 1.0761x; 1.0761x over previous
#include <cuda_runtime.h>
#include <cuda_fp16.h>
#include <math.h>

#define N_ATOMS 50000
#define N_EDGES 400000
#define N_MOLS  500
#define HID     128
#define NRBF    20
#define NLAYERS 4
#define NV      (N_ATOMS * HID)

#define TAB_D   512
#define TAB_MAX 12.0f
#define RBF_STEP (5.0f / (float)(NRBF - 1))

typedef unsigned long long ull;
typedef unsigned int uint;

// ---------------- device scratch ----------------
__device__ float  g_s[NV];            // fp32 master s
__device__ __half g_sh[NV];           // half mirror
__device__ __half g_vh[3 * NV];       // half v
__device__ __half g_ms[NV];           // half m_s
__device__ __half g_vn[NV];           // half ||m_v||
__device__ __half g_mvh[3 * NV];      // half m_v
__device__ __half2 g_htabh[NLAYERS * TAB_D * 3 * HID];
__device__ float g_hmol[N_MOLS * HID];
__device__ float g_cnt[N_MOLS];

// CSR scratch
__device__ int   g_deg[N_ATOMS];
__device__ int   g_rowptr[N_ATOMS + 1];
__device__ int   g_cursor[N_ATOMS];
__device__ int   g_bsum[128];
__device__ int   g_ecol[N_EDGES];
__device__ float4 g_egeo[N_EDGES];

__device__ __forceinline__ float silu_f(float x) { return x / (1.0f + expf(-x)); }

__device__ __forceinline__ uint f2tf32(float x) {
    uint r;
    asm("cvt.rna.tf32.f32 %0, %1;" : "=r"(r) : "f"(x));
    return r;
}
__device__ __forceinline__ float tf32f(float x) { return __uint_as_float(f2tf32(x)); }

__device__ __forceinline__ void mma_tf32(float* c, uint a0, uint a1, uint a2, uint a3,
                                         uint b0, uint b1) {
    asm("mma.sync.aligned.m16n8k8.row.col.f32.tf32.tf32.f32 "
        "{%0,%1,%2,%3},{%4,%5,%6,%7},{%8,%9},{%0,%1,%2,%3};"
        : "+f"(c[0]), "+f"(c[1]), "+f"(c[2]), "+f"(c[3])
        : "r"(a0), "r"(a1), "r"(a2), "r"(a3), "r"(b0), "r"(b1));
}

__device__ __forceinline__ float4 h4_to_f4(uint2 u) {
    __half2 h01 = *(__half2*)&u.x;
    __half2 h23 = *(__half2*)&u.y;
    float2 a = __half22float2(h01);
    float2 b = __half22float2(h23);
    return make_float4(a.x, a.y, b.x, b.y);
}
__device__ __forceinline__ uint2 f4_to_h4(float x, float y, float z, float w) {
    __half2 h01 = __floats2half2_rn(x, y);
    __half2 h23 = __floats2half2_rn(z, w);
    uint2 r;
    r.x = *(unsigned*)&h01;
    r.y = *(unsigned*)&h23;
    return r;
}

// ---------------- init (also zeroes pooling buffers) ----------------
__global__ void init_kernel(const int* __restrict__ z, const float* __restrict__ emb) {
    int idx = blockIdx.x * blockDim.x + threadIdx.x;
    if (idx < N_ATOMS) g_deg[idx] = 0;
    if (idx < N_MOLS * HID) g_hmol[idx] = 0.f;
    if (idx < N_MOLS) g_cnt[idx] = 0.f;
    if (idx >= NV) return;
    int n = idx >> 7;
    int j = idx & 127;
    float s = emb[z[n] * HID + j];
    g_s[idx] = s;
    g_sh[idx] = __float2half(s);
}

// ---------------- CSR build ----------------
__global__ void hist_kernel(const int* __restrict__ ei) {
    int e = blockIdx.x * blockDim.x + threadIdx.x;
    if (e >= N_EDGES) return;
    atomicAdd(&g_deg[ei[e]], 1);
}

#define SCAN_B 512
__global__ void scan1_kernel() {
    __shared__ int s[SCAN_B];
    int t = threadIdx.x;
    int i = blockIdx.x * SCAN_B + t;
    int v = (i < N_ATOMS) ? g_deg[i] : 0;
    s[t] = v;
    __syncthreads();
    for (int off = 1; off < SCAN_B; off <<= 1) {
        int add = (t >= off) ? s[t - off] : 0;
        __syncthreads();
        s[t] += add;
        __syncthreads();
    }
    if (i < N_ATOMS) g_rowptr[i] = s[t] - v;
    if (t == SCAN_B - 1) g_bsum[blockIdx.x] = s[t];
}

__global__ void scan2_kernel(int nblocks) {
    __shared__ int s[128];
    int t = threadIdx.x;
    int v = (t < nblocks) ? g_bsum[t] : 0;
    s[t] = v;
    __syncthreads();
    for (int off = 1; off < 128; off <<= 1) {
        int add = (t >= off) ? s[t - off] : 0;
        __syncthreads();
        s[t] += add;
        __syncthreads();
    }
    if (t < nblocks) g_bsum[t] = s[t] - v;
}

__global__ void scan3_kernel(const int* __restrict__ batch) {
    int i = blockIdx.x * blockDim.x + threadIdx.x;
    if (i < N_ATOMS) {
        int rp = g_rowptr[i] + g_bsum[i >> 9];
        g_rowptr[i] = rp;
        g_cursor[i] = rp;
        atomicAdd(&g_cnt[batch[i]], 1.0f);
    }
    if (i == 0) g_rowptr[N_ATOMS] = N_EDGES;
}

__global__ void scatter_kernel(const int* __restrict__ ei, const float* __restrict__ pos) {
    int e = blockIdx.x * blockDim.x + threadIdx.x;
    if (e >= N_EDGES) return;
    int r = ei[e];
    int c = ei[N_EDGES + e];
    float dx = pos[c * 3 + 0] - pos[r * 3 + 0];
    float dy = pos[c * 3 + 1] - pos[r * 3 + 1];
    float dz = pos[c * 3 + 2] - pos[r * 3 + 2];
    float dist = sqrtf(dx * dx + dy * dy + dz * dz);
    float inv = 1.0f / (dist + 1e-8f);
    const float INV_DELTA = (float)(TAB_D - 1) / TAB_MAX;
    int p = atomicAdd(&g_cursor[r], 1);
    g_ecol[p] = c;
    g_egeo[p] = make_float4(dx * inv, dy * inv, dz * inv, dist * INV_DELTA);
}

// ---------------- filter table build ----------------
#define TAB_SMEM_FLOATS 20736

extern "C" __global__ void __launch_bounds__(512, 1)
table_kernel(const float* __restrict__ fW1, const float* __restrict__ fb1,
             const float* __restrict__ fW2, const float* __restrict__ fb2) {
    extern __shared__ float sm[];
    float* hid = sm;
    float* rbf_s = sm + 8448;
    float* w1_s = sm + 9728;
    float* w2_s = sm + 8448;

    const int tid = threadIdx.x;
    const int layer = blockIdx.y;
    const int g0 = blockIdx.x * 64;
    const float* W1 = fW1 + layer * NRBF * HID;
    const float* b1 = fb1 + layer * HID;
    const float* W2 = fW2 + layer * HID * 3 * HID;
    const float* b2 = fb2 + layer * 3 * HID;
    const float DELTA = TAB_MAX / (float)(TAB_D - 1);

    for (int idx = tid; idx < 64 * NRBF; idx += 512) {
        int e = idx / NRBF, k = idx % NRBF;
        float d = (float)(g0 + e) * DELTA - RBF_STEP * (float)k;
        rbf_s[idx] = expf(-d * d);
    }
    for (int idx = tid; idx < NRBF * HID; idx += 512) w1_s[idx] = W1[idx];
    __syncthreads();

    const int jg = tid & 31;
    const int eg = tid >> 5;
    const int j0 = jg * 4;
    const int el0 = eg * 4;

    float hacc[4][4];
#pragma unroll
    for (int a = 0; a < 4; a++)
#pragma unroll
        for (int b = 0; b < 4; b++) hacc[a][b] = b1[j0 + b];
#pragma unroll
    for (int k = 0; k < NRBF; k++) {
        float r[4];
#pragma unroll
        for (int a = 0; a < 4; a++) r[a] = rbf_s[(el0 + a) * NRBF + k];
        float4 w = *(const float4*)&w1_s[k * HID + j0];
        float wv[4] = {w.x, w.y, w.z, w.w};
#pragma unroll
        for (int a = 0; a < 4; a++)
#pragma unroll
            for (int b = 0; b < 4; b++) hacc[a][b] += r[a] * wv[b];
    }
#pragma unroll
    for (int a = 0; a < 4; a++)
#pragma unroll
        for (int b = 0; b < 4; b++) hid[(el0 + a) * 132 + j0 + b] = silu_f(hacc[a][b]);
    __syncthreads();

    float a_ss[4][4], a_vv[4][4], a_sv[4][4];
#pragma unroll
    for (int a = 0; a < 4; a++)
#pragma unroll
        for (int b = 0; b < 4; b++) { a_ss[a][b] = 0.f; a_vv[a][b] = 0.f; a_sv[a][b] = 0.f; }

    for (int kc = 0; kc < HID; kc += 32) {
        __syncthreads();
        for (int idx = tid; idx < 32 * 384; idx += 512) w2_s[idx] = W2[kc * 384 + idx];
        __syncthreads();
#pragma unroll 8
        for (int kk = 0; kk < 32; kk++) {
            float h[4];
#pragma unroll
            for (int a = 0; a < 4; a++) h[a] = hid[(el0 + a) * 132 + kc + kk];
            float4 wss = *(const float4*)&w2_s[kk * 384 + j0];
            float4 wvv = *(const float4*)&w2_s[kk * 384 + 128 + j0];
            float4 wsv = *(const float4*)&w2_s[kk * 384 + 256 + j0];
            float ss[4] = {wss.x, wss.y, wss.z, wss.w};
            float vv[4] = {wvv.x, wvv.y, wvv.z, wvv.w};
            float sv[4] = {wsv.x, wsv.y, wsv.z, wsv.w};
#pragma unroll
            for (int a = 0; a < 4; a++)
#pragma unroll
                for (int b = 0; b < 4; b++) {
                    a_ss[a][b] += h[a] * ss[b];
                    a_vv[a][b] += h[a] * vv[b];
                    a_sv[a][b] += h[a] * sv[b];
                }
        }
    }

#pragma unroll
    for (int a = 0; a < 4; a++) {
        int gi = g0 + el0 + a;
        __half* Tx = (__half*)(g_htabh + ((size_t)layer * TAB_D + gi) * 384);
        __half* Ty = (__half*)(g_htabh + ((size_t)layer * TAB_D + gi - 1) * 384);
#pragma unroll
        for (int b = 0; b < 4; b++) {
            int ch = j0 + b;
            float hss = a_ss[a][b] + b2[ch];
            float hvv = a_vv[a][b] + b2[128 + ch];
            float hsv = a_sv[a][b] + b2[256 + ch];
            Tx[(0 * 128 + ch) * 2] = __float2half(hss);
            Tx[(1 * 128 + ch) * 2] = __float2half(hvv);
            Tx[(2 * 128 + ch) * 2] = __float2half(hsv);
            if (gi > 0) {
                Ty[(0 * 128 + ch) * 2 + 1] = __float2half(hss);
                Ty[(1 * 128 + ch) * 2 + 1] = __float2half(hvv);
                Ty[(2 * 128 + ch) * 2 + 1] = __float2half(hsv);
            }
        }
    }
}

// ---------------- edge message kernel (R10 form) ----------------
extern "C" __global__ void __launch_bounds__(256)
msg_kernel(int layer) {
    int r = (blockIdx.x * 256 + threadIdx.x) >> 5;
    int lane = threadIdx.x & 31;
    if (r >= N_ATOMS) return;

    int beg = g_rowptr[r];
    int end = g_rowptr[r + 1];
    int base = r * HID + lane * 4;

    if (beg >= end) {
        uint2 z; z.x = 0u; z.y = 0u;
        *(uint2*)&g_ms[base] = z;
        *(uint2*)&g_vn[base] = z;
        *(uint2*)&g_mvh[0 * NV + base] = z;
        *(uint2*)&g_mvh[1 * NV + base] = z;
        *(uint2*)&g_mvh[2 * NV + base] = z;
        return;
    }

    const bool hasv = (layer != 0);
    const __half2* Tl = g_htabh + (size_t)layer * TAB_D * 384;

    float accS[4] = {0.f, 0.f, 0.f, 0.f};
    float accV[12];
#pragma unroll
    for (int q = 0; q < 12; q++) accV[q] = 0.f;

    int colN = __ldg(&g_ecol[beg]);
    float4 geoN = __ldg(&g_egeo[beg]);
    float fN;
    const uint4* TbN;
    {
        float u = geoN.w;
        int i0 = (int)u;
        if (i0 > TAB_D - 2) i0 = TAB_D - 2;
        fN = fminf(u - (float)i0, 1.0f);
        TbN = (const uint4*)(Tl + (size_t)i0 * 384);
    }
    uint4 t0N = __ldg(&TbN[lane]);
    uint4 t1N = __ldg(&TbN[32 + lane]);
    uint4 t2N = __ldg(&TbN[64 + lane]);
    uint2 sN = __ldcg((const uint2*)&g_sh[colN * HID + lane * 4]);
    uint2 v0N, v1N, v2N;
    v0N.x = v0N.y = v1N.x = v1N.y = v2N.x = v2N.y = 0u;
    if (hasv) {
        v0N = __ldcg((const uint2*)&g_vh[0 * NV + colN * HID + lane * 4]);
        v1N = __ldcg((const uint2*)&g_vh[1 * NV + colN * HID + lane * 4]);
        v2N = __ldcg((const uint2*)&g_vh[2 * NV + colN * HID + lane * 4]);
    }

    for (int p = beg; p < end; p++) {
        float4 geo = geoN;
        float f = fN;
        uint4 t0 = t0N, t1 = t1N, t2 = t2N;
        uint2 sv = sN, v0 = v0N, v1 = v1N, v2 = v2N;

        if (p + 1 < end) {
            int colX = __ldg(&g_ecol[p + 1]);
            geoN = __ldg(&g_egeo[p + 1]);
            float u = geoN.w;
            int i0 = (int)u;
            if (i0 > TAB_D - 2) i0 = TAB_D - 2;
            fN = fminf(u - (float)i0, 1.0f);
            TbN = (const uint4*)(Tl + (size_t)i0 * 384);
            t0N = __ldg(&TbN[lane]);
            t1N = __ldg(&TbN[32 + lane]);
            t2N = __ldg(&TbN[64 + lane]);
            sN = __ldcg((const uint2*)&g_sh[colX * HID + lane * 4]);
            if (hasv) {
                v0N = __ldcg((const uint2*)&g_vh[0 * NV + colX * HID + lane * 4]);
                v1N = __ldcg((const uint2*)&g_vh[1 * NV + colX * HID + lane * 4]);
                v2N = __ldcg((const uint2*)&g_vh[2 * NV + colX * HID + lane * 4]);
            }
        }

        float4 scf = h4_to_f4(sv);
        float sc[4] = {scf.x, scf.y, scf.z, scf.w};
        float vc0[4], vc1[4], vc2[4];
        if (hasv) {
            float4 a0 = h4_to_f4(v0);
            float4 a1 = h4_to_f4(v1);
            float4 a2 = h4_to_f4(v2);
            vc0[0] = a0.x; vc0[1] = a0.y; vc0[2] = a0.z; vc0[3] = a0.w;
            vc1[0] = a1.x; vc1[1] = a1.y; vc1[2] = a1.z; vc1[3] = a1.w;
            vc2[0] = a2.x; vc2[1] = a2.y; vc2[2] = a2.z; vc2[3] = a2.w;
        }

        const __half2* e0 = (const __half2*)&t0;
        const __half2* e1 = (const __half2*)&t1;
        const __half2* e2 = (const __half2*)&t2;
#pragma unroll
        for (int c = 0; c < 4; c++) {
            float2 pss = __half22float2(e0[c]);
            float2 pvv = __half22float2(e1[c]);
            float2 psv = __half22float2(e2[c]);
            float hss = pss.x + f * (pss.y - pss.x);
            float hvv = pvv.x + f * (pvv.y - pvv.x);
            float hsv = psv.x + f * (psv.y - psv.x);
            accS[c] += hss * sc[c];
            float cc = hsv * sc[c];
            if (hasv) {
                accV[c]     += hvv * vc0[c] + cc * geo.x;
                accV[4 + c] += hvv * vc1[c] + cc * geo.y;
                accV[8 + c] += hvv * vc2[c] + cc * geo.z;
            } else {
                accV[c]     += cc * geo.x;
                accV[4 + c] += cc * geo.y;
                accV[8 + c] += cc * geo.z;
            }
        }
    }

    *(uint2*)&g_ms[base] = f4_to_h4(accS[0], accS[1], accS[2], accS[3]);
    float vn[4];
#pragma unroll
    for (int c = 0; c < 4; c++)
        vn[c] = sqrtf(accV[c] * accV[c] + accV[4 + c] * accV[4 + c] + accV[8 + c] * accV[8 + c]);
    *(uint2*)&g_vn[base] = f4_to_h4(vn[0], vn[1], vn[2], vn[3]);
    *(uint2*)&g_mvh[0 * NV + base] = f4_to_h4(accV[0], accV[1], accV[2], accV[3]);
    *(uint2*)&g_mvh[1 * NV + base] = f4_to_h4(accV[4], accV[5], accV[6], accV[7]);
    *(uint2*)&g_mvh[2 * NV + base] = f4_to_h4(accV[8], accV[9], accV[10], accV[11]);
}

// ---------------- node update kernel (tf32 mma.sync; fused pooling on last layer) ----------------
#define NT 64
#define XS_STRIDE 76
#define WC_STRIDE 132
#define NODE_SMEM_FLOATS 23040

extern "C" __global__ void __launch_bounds__(256, 2)
node_kernel(int layer, const int* __restrict__ batch,
            const float* __restrict__ uW1, const float* __restrict__ ub1,
            const float* __restrict__ uW2, const float* __restrict__ ub2) {
    extern __shared__ float sm[];
    float* xs_t = sm;
    float* wc   = sm + 4864;
    float* ts_t = sm + 13312;
    __half* alpha_s = (__half*)sm;

    const int tid = threadIdx.x;
    const int n0 = blockIdx.x * NT;
    const float* W1 = uW1 + layer * 384 * HID;
    const float* b1 = ub1 + layer * HID;
    const float* W2 = uW2 + layer * HID * 384;
    const float* b2 = ub2 + layer * 384;

    const int w = tid >> 5;
    const int lane = tid & 31;
    const int gid = lane >> 2;
    const int tig = lane & 3;
    const int wn2 = w >> 2;
    const int wcq = w & 3;
    const int nbase = 32 * wn2 + gid;
    const int cbase = 32 * wcq + gid;

    const int snode = tid & 63;
    const int sq = (tid >> 6) << 2;
    const int sgn = n0 + snode;
    const bool svalid = (sgn < N_ATOMS);

    float4 wreg[8];
#pragma unroll
    for (int q = 0; q < 8; q++) {
        int idx = q * 256 + tid;
        int k = idx >> 5, c4 = idx & 31;
        wreg[q] = *(const float4*)&W1[k * HID + c4 * 4];
    }

    float4 xpre[4];
    {
        const float* sp = g_s + (size_t)sgn * HID;
#pragma unroll
        for (int q = 0; q < 4; q++)
            xpre[q] = svalid ? *(const float4*)&sp[sq + 16 * q]
                             : make_float4(0.f, 0.f, 0.f, 0.f);
    }

    // ---- stage 1: T = silu(X @ W1 + b1) ----
    float c1r[2][4][4];
#pragma unroll
    for (int nt = 0; nt < 4; nt++) {
        int cl = 32 * wcq + 8 * nt + 2 * tig;
        float bb0 = b1[cl], bb1 = b1[cl + 1];
#pragma unroll
        for (int mt = 0; mt < 2; mt++) {
            c1r[mt][nt][0] = bb0; c1r[mt][nt][1] = bb1;
            c1r[mt][nt][2] = bb0; c1r[mt][nt][3] = bb1;
        }
    }

    for (int kc = 0; kc < 384; kc += 64) {
        __syncthreads();
#pragma unroll
        for (int q = 0; q < 8; q++) {
            int idx = q * 256 + tid;
            int k = idx >> 5, c4 = idx & 31;
            *(float4*)&wc[k * WC_STRIDE + c4 * 4] =
                make_float4(tf32f(wreg[q].x), tf32f(wreg[q].y),
                            tf32f(wreg[q].z), tf32f(wreg[q].w));
        }
#pragma unroll
        for (int q = 0; q < 4; q++) {
            int kl = sq + 16 * q;
            xs_t[(kl + 0) * XS_STRIDE + snode] = tf32f(xpre[q].x);
            xs_t[(kl + 1) * XS_STRIDE + snode] = tf32f(xpre[q].y);
            xs_t[(kl + 2) * XS_STRIDE + snode] = tf32f(xpre[q].z);
            xs_t[(kl + 3) * XS_STRIDE + snode] = tf32f(xpre[q].w);
        }
        __syncthreads();
        if (kc + 64 < 384) {
            int nkc = kc + 64;
#pragma unroll
            for (int q = 0; q < 8; q++) {
                int idx = q * 256 + tid;
                int k = idx >> 5, c4 = idx & 31;
                wreg[q] = *(const float4*)&W1[(nkc + k) * HID + c4 * 4];
            }
            if (nkc < 128) {
                const float* sp = g_s + (size_t)sgn * HID + nkc;
#pragma unroll
                for (int q = 0; q < 4; q++)
                    xpre[q] = svalid ? *(const float4*)&sp[sq + 16 * q]
                                     : make_float4(0.f, 0.f, 0.f, 0.f);
            } else {
                const __half* hp = ((nkc < 256) ? g_ms : g_vn) + (size_t)sgn * HID + (nkc & 127);
#pragma unroll
                for (int q = 0; q < 4; q++)
                    xpre[q] = svalid ? h4_to_f4(*(const uint2*)&hp[sq + 16 * q])
                                     : make_float4(0.f, 0.f, 0.f, 0.f);
            }
        } else {
#pragma unroll
            for (int q = 0; q < 8; q++) {
                int idx = q * 256 + tid;
                int k = idx >> 5, c4 = idx & 31;
                wreg[q] = *(const float4*)&W2[k * 384 + c4 * 4];
            }
        }
#pragma unroll
        for (int kk8 = 0; kk8 < 8; kk8++) {
            int kb = kk8 * 8;
            const float* xr0 = &xs_t[(kb + tig) * XS_STRIDE];
            const float* xr1 = &xs_t[(kb + tig + 4) * XS_STRIDE];
            uint a[2][4];
#pragma unroll
            for (int mt = 0; mt < 2; mt++) {
                int nb = nbase + 16 * mt;
                a[mt][0] = __float_as_uint(xr0[nb]);
                a[mt][1] = __float_as_uint(xr0[nb + 8]);
                a[mt][2] = __float_as_uint(xr1[nb]);
                a[mt][3] = __float_as_uint(xr1[nb + 8]);
            }
            const float* wr0 = &wc[(kb + tig) * WC_STRIDE];
            const float* wr1 = &wc[(kb + tig + 4) * WC_STRIDE];
#pragma unroll
            for (int nt = 0; nt < 4; nt++) {
                uint b0 = __float_as_uint(wr0[cbase + 8 * nt]);
                uint b1u = __float_as_uint(wr1[cbase + 8 * nt]);
                mma_tf32(c1r[0][nt], a[0][0], a[0][1], a[0][2], a[0][3], b0, b1u);
                mma_tf32(c1r[1][nt], a[1][0], a[1][1], a[1][2], a[1][3], b0, b1u);
            }
        }
    }

#pragma unroll
    for (int mt = 0; mt < 2; mt++) {
        int lr = 32 * wn2 + 16 * mt + gid;
#pragma unroll
        for (int nt = 0; nt < 4; nt++) {
            int cl = 32 * wcq + 8 * nt + 2 * tig;
            ts_t[(cl + 0) * XS_STRIDE + lr]     = tf32f(silu_f(c1r[mt][nt][0]));
            ts_t[(cl + 1) * XS_STRIDE + lr]     = tf32f(silu_f(c1r[mt][nt][1]));
            ts_t[(cl + 0) * XS_STRIDE + lr + 8] = tf32f(silu_f(c1r[mt][nt][2]));
            ts_t[(cl + 1) * XS_STRIDE + lr + 8] = tf32f(silu_f(c1r[mt][nt][3]));
        }
    }

    // ---- stage 2: U = T @ W2 + b2 ----
    float u2r[2][4][4];
    for (int c = 0; c < 6; c++) {
        int jb = c >> 1;
        int kc2 = (c & 1) * 64;
        if (kc2 == 0) {
#pragma unroll
            for (int mt = 0; mt < 2; mt++)
#pragma unroll
                for (int nt = 0; nt < 4; nt++)
#pragma unroll
                    for (int x = 0; x < 4; x++) u2r[mt][nt][x] = 0.f;
        }
        __syncthreads();
#pragma unroll
        for (int q = 0; q < 8; q++) {
            int idx = q * 256 + tid;
            int k = idx >> 5, c4 = idx & 31;
            *(float4*)&wc[k * WC_STRIDE + c4 * 4] =
                make_float4(tf32f(wreg[q].x), tf32f(wreg[q].y),
                            tf32f(wreg[q].z), tf32f(wreg[q].w));
        }
        __syncthreads();
        if (c < 5) {
            int cn = c + 1;
            int jbn = cn >> 1;
            int kc2n = (cn & 1) * 64;
#pragma unroll
            for (int q = 0; q < 8; q++) {
                int idx = q * 256 + tid;
                int k = idx >> 5, c4 = idx & 31;
                wreg[q] = *(const float4*)&W2[(kc2n + k) * 384 + jbn * 128 + c4 * 4];
            }
        }
#pragma unroll
        for (int kk8 = 0; kk8 < 8; kk8++) {
            int kb = kk8 * 8;
            const float* tr0 = &ts_t[(kc2 + kb + tig) * XS_STRIDE];
            const float* tr1 = &ts_t[(kc2 + kb + tig + 4) * XS_STRIDE];
            uint a[2][4];
#pragma unroll
            for (int mt = 0; mt < 2; mt++) {
                int nb = nbase + 16 * mt;
                a[mt][0] = __float_as_uint(tr0[nb]);
                a[mt][1] = __float_as_uint(tr0[nb + 8]);
                a[mt][2] = __float_as_uint(tr1[nb]);
                a[mt][3] = __float_as_uint(tr1[nb + 8]);
            }
            const float* wr0 = &wc[(kb + tig) * WC_STRIDE];
            const float* wr1 = &wc[(kb + tig + 4) * WC_STRIDE];
#pragma unroll
            for (int nt = 0; nt < 4; nt++) {
                uint b0 = __float_as_uint(wr0[cbase + 8 * nt]);
                uint b1u = __float_as_uint(wr1[cbase + 8 * nt]);
                mma_tf32(u2r[0][nt], a[0][0], a[0][1], a[0][2], a[0][3], b0, b1u);
                mma_tf32(u2r[1][nt], a[1][0], a[1][1], a[1][2], a[1][3], b0, b1u);
            }
        }

        if (kc2 == 64) {
#pragma unroll
            for (int mt = 0; mt < 2; mt++) {
#pragma unroll
                for (int rs = 0; rs < 2; rs++) {
                    int lr = 32 * wn2 + 16 * mt + gid + rs * 8;
                    int gn = n0 + lr;
                    if (gn >= N_ATOMS) continue;
#pragma unroll
                    for (int nt = 0; nt < 4; nt++) {
                        int j = 32 * wcq + 8 * nt + 2 * tig;
                        float u0 = u2r[mt][nt][rs * 2 + 0] + b2[jb * 128 + j];
                        float u1 = u2r[mt][nt][rs * 2 + 1] + b2[jb * 128 + j + 1];
                        if (jb == 0) {
                            float2* sp = (float2*)&g_s[gn * HID + j];
                            float2 s = *sp;
                            s.x += u0; s.y += u1;
                            *sp = s;
                            *(__half2*)&g_sh[gn * HID + j] = __floats2half2_rn(s.x, s.y);
                            if (layer == NLAYERS - 1) {
                                int m = batch[gn];
                                atomicAdd(&g_hmol[m * HID + j], s.x);
                                atomicAdd(&g_hmol[m * HID + j + 1], s.y);
                            }
                        } else if (jb == 1) {
                            *(__half2*)&alpha_s[lr * HID + j] = __floats2half2_rn(u0, u1);
                        } else {
                            float2 al = __half22float2(*(__half2*)&alpha_s[lr * HID + j]);
#pragma unroll
                            for (int d = 0; d < 3; d++) {
                                float2 mv = __half22float2(*(__half2*)&g_mvh[d * NV + gn * HID + j]);
                                float2 vo = make_float2(0.f, 0.f);
                                if (layer != 0)
                                    vo = __half22float2(*(__half2*)&g_vh[d * NV + gn * HID + j]);
                                float nx = al.x * vo.x + u0 * mv.x;
                                float ny = al.y * vo.y + u1 * mv.y;
                                *(__half2*)&g_vh[d * NV + gn * HID + j] = __floats2half2_rn(nx, ny);
                            }
                        }
                    }
                }
            }
        }
    }
}

// ---------------- heads ----------------
__global__ void head_kernel(const float* __restrict__ lW1, const float* __restrict__ lb1,
                            const float* __restrict__ lW2, const float* __restrict__ lb2,
                            const float* __restrict__ pW1, const float* __restrict__ pb1,
                            const float* __restrict__ pW2, const float* __restrict__ pb2,
                            float* __restrict__ out) {
    __shared__ float hm[HID];
    __shared__ float tt[HID];
    __shared__ float red[HID];
    int m = blockIdx.x;
    int j = threadIdx.x;
    float cnt = g_cnt[m];
    hm[j] = g_hmol[m * HID + j] / cnt;
    __syncthreads();

    float acc = lb1[j];
    for (int k = 0; k < HID; k++) acc += hm[k] * lW1[k * HID + j];
    tt[j] = silu_f(acc);
    __syncthreads();
    red[j] = tt[j] * lW2[j];
    __syncthreads();
    for (int s = 64; s > 0; s >>= 1) {
        if (j < s) red[j] += red[j + s];
        __syncthreads();
    }
    if (j == 0) out[m] = red[0] + lb2[0];
    __syncthreads();

    acc = pb1[j];
    for (int k = 0; k < HID; k++) acc += hm[k] * pW1[k * HID + j];
    tt[j] = silu_f(acc);
    __syncthreads();
    red[j] = tt[j] * pW2[j];
    __syncthreads();
    for (int s = 64; s > 0; s >>= 1) {
        if (j < s) red[j] += red[j + s];
        __syncthreads();
    }
    if (j == 0) {
        float x = red[0] + pb2[0];
        out[N_MOLS + m] = 1.0f / (1.0f + expf(-x));
    }
}

// ---------------- launch ----------------
extern "C" void kernel_launch(void* const* d_in, const int* in_sizes, int n_in,
                              void* d_out, int out_size) {
    const int* z = (const int*)d_in[0];
    const float* pos = (const float*)d_in[1];
    const int* ei = (const int*)d_in[2];
    const int* batch = (const int*)d_in[3];
    const float* emb = (const float*)d_in[4];
    const float* fW1 = (const float*)d_in[5];
    const float* fb1 = (const float*)d_in[6];
    const float* fW2 = (const float*)d_in[7];
    const float* fb2 = (const float*)d_in[8];
    const float* uW1 = (const float*)d_in[9];
    const float* ub1 = (const float*)d_in[10];
    const float* uW2 = (const float*)d_in[11];
    const float* ub2 = (const float*)d_in[12];
    const float* lW1 = (const float*)d_in[13];
    const float* lb1 = (const float*)d_in[14];
    const float* lW2 = (const float*)d_in[15];
    const float* lb2 = (const float*)d_in[16];
    const float* pW1 = (const float*)d_in[17];
    const float* pb1 = (const float*)d_in[18];
    const float* pW2 = (const float*)d_in[19];
    const float* pb2 = (const float*)d_in[20];
    float* out = (float*)d_out;

    cudaFuncSetAttribute(table_kernel, cudaFuncAttributeMaxDynamicSharedMemorySize,
                         TAB_SMEM_FLOATS * 4);
    cudaFuncSetAttribute(node_kernel, cudaFuncAttributeMaxDynamicSharedMemorySize,
                         NODE_SMEM_FLOATS * 4);

    init_kernel<<<(NV + 255) / 256, 256>>>(z, emb);

    const int scan_blocks = (N_ATOMS + SCAN_B - 1) / SCAN_B;
    hist_kernel<<<(N_EDGES + 255) / 256, 256>>>(ei);
    scan1_kernel<<<scan_blocks, SCAN_B>>>();
    scan2_kernel<<<1, 128>>>(scan_blocks);
    scan3_kernel<<<(N_ATOMS + 255) / 256, 256>>>(batch);
    scatter_kernel<<<(N_EDGES + 255) / 256, 256>>>(ei, pos);

    table_kernel<<<dim3(TAB_D / 64, NLAYERS), 512, TAB_SMEM_FLOATS * 4>>>(fW1, fb1, fW2, fb2);

    const int msg_blocks = (N_ATOMS * 32 + 255) / 256;
    const int node_blocks = (N_ATOMS + NT - 1) / NT;
    for (int layer = 0; layer < NLAYERS; layer++) {
        msg_kernel<<<msg_blocks, 256>>>(layer);
        node_kernel<<<node_blocks, 256, NODE_SMEM_FLOATS * 4>>>(layer, batch, uW1, ub1, uW2, ub2);
    }

    head_kernel<<<N_MOLS, HID>>>(lW1, lb1, lW2, lb2, pW1, pb1, pW2, pb2, out);
}

// round 17
// speedup vs baseline: 1.1300x; 1.0501x over previous
#include <cuda_runtime.h>
#include <cuda_fp16.h>
#include <math.h>

#define N_ATOMS 50000
#define N_EDGES 400000
#define N_MOLS  500
#define HID     128
#define NRBF    20
#define NLAYERS 4
#define NV      (N_ATOMS * HID)

#define TAB_D   4096
#define TAB_MAX 12.0f
#define RBF_STEP (5.0f / (float)(NRBF - 1))

typedef unsigned long long ull;
typedef unsigned int uint;

// ---------------- device scratch ----------------
__device__ float  g_s[NV];            // fp32 master s
__device__ __half g_sh[NV];           // half mirror
__device__ __half g_vh[3 * NV];       // half v
__device__ __half g_ms[NV];           // half m_s
__device__ __half g_vn[NV];           // half ||m_v||
__device__ __half g_mvh[3 * NV];      // half m_v
__device__ __half g_htab1[(size_t)NLAYERS * TAB_D * 3 * HID];  // single-value NN table
__device__ float g_hmol[N_MOLS * HID];
__device__ float g_cnt[N_MOLS];

// CSR scratch
__device__ int   g_deg[N_ATOMS];
__device__ int   g_rowptr[N_ATOMS + 1];
__device__ int   g_cursor[N_ATOMS];
__device__ int   g_bsum[128];
__device__ int   g_ecol[N_EDGES];
__device__ float4 g_egeo[N_EDGES];

__device__ __forceinline__ float silu_f(float x) { return x / (1.0f + expf(-x)); }

__device__ __forceinline__ uint f2tf32(float x) {
    uint r;
    asm("cvt.rna.tf32.f32 %0, %1;" : "=r"(r) : "f"(x));
    return r;
}
__device__ __forceinline__ float tf32f(float x) { return __uint_as_float(f2tf32(x)); }

__device__ __forceinline__ void mma_tf32(float* c, uint a0, uint a1, uint a2, uint a3,
                                         uint b0, uint b1) {
    asm("mma.sync.aligned.m16n8k8.row.col.f32.tf32.tf32.f32 "
        "{%0,%1,%2,%3},{%4,%5,%6,%7},{%8,%9},{%0,%1,%2,%3};"
        : "+f"(c[0]), "+f"(c[1]), "+f"(c[2]), "+f"(c[3])
        : "r"(a0), "r"(a1), "r"(a2), "r"(a3), "r"(b0), "r"(b1));
}

__device__ __forceinline__ float4 h4_to_f4(uint2 u) {
    __half2 h01 = *(__half2*)&u.x;
    __half2 h23 = *(__half2*)&u.y;
    float2 a = __half22float2(h01);
    float2 b = __half22float2(h23);
    return make_float4(a.x, a.y, b.x, b.y);
}
__device__ __forceinline__ uint2 f4_to_h4(float x, float y, float z, float w) {
    __half2 h01 = __floats2half2_rn(x, y);
    __half2 h23 = __floats2half2_rn(z, w);
    uint2 r;
    r.x = *(unsigned*)&h01;
    r.y = *(unsigned*)&h23;
    return r;
}

// ---------------- init ----------------
__global__ void init_kernel(const int* __restrict__ z, const float* __restrict__ emb) {
    int idx = blockIdx.x * blockDim.x + threadIdx.x;
    if (idx < N_ATOMS) g_deg[idx] = 0;
    if (idx < N_MOLS * HID) g_hmol[idx] = 0.f;
    if (idx < N_MOLS) g_cnt[idx] = 0.f;
    if (idx >= NV) return;
    int n = idx >> 7;
    int j = idx & 127;
    float s = emb[z[n] * HID + j];
    g_s[idx] = s;
    g_sh[idx] = __float2half(s);
}

// ---------------- CSR build ----------------
__global__ void hist_kernel(const int* __restrict__ ei) {
    int e = blockIdx.x * blockDim.x + threadIdx.x;
    if (e >= N_EDGES) return;
    atomicAdd(&g_deg[ei[e]], 1);
}

#define SCAN_B 512
__global__ void scan1_kernel() {
    __shared__ int s[SCAN_B];
    int t = threadIdx.x;
    int i = blockIdx.x * SCAN_B + t;
    int v = (i < N_ATOMS) ? g_deg[i] : 0;
    s[t] = v;
    __syncthreads();
    for (int off = 1; off < SCAN_B; off <<= 1) {
        int add = (t >= off) ? s[t - off] : 0;
        __syncthreads();
        s[t] += add;
        __syncthreads();
    }
    if (i < N_ATOMS) g_rowptr[i] = s[t] - v;
    if (t == SCAN_B - 1) g_bsum[blockIdx.x] = s[t];
}

__global__ void scan2_kernel(int nblocks) {
    __shared__ int s[128];
    int t = threadIdx.x;
    int v = (t < nblocks) ? g_bsum[t] : 0;
    s[t] = v;
    __syncthreads();
    for (int off = 1; off < 128; off <<= 1) {
        int add = (t >= off) ? s[t - off] : 0;
        __syncthreads();
        s[t] += add;
        __syncthreads();
    }
    if (t < nblocks) g_bsum[t] = s[t] - v;
}

__global__ void scan3_kernel(const int* __restrict__ batch) {
    int i = blockIdx.x * blockDim.x + threadIdx.x;
    if (i < N_ATOMS) {
        int rp = g_rowptr[i] + g_bsum[i >> 9];
        g_rowptr[i] = rp;
        g_cursor[i] = rp;
        atomicAdd(&g_cnt[batch[i]], 1.0f);
    }
    if (i == 0) g_rowptr[N_ATOMS] = N_EDGES;
}

__global__ void scatter_kernel(const int* __restrict__ ei, const float* __restrict__ pos) {
    int e = blockIdx.x * blockDim.x + threadIdx.x;
    if (e >= N_EDGES) return;
    int r = ei[e];
    int c = ei[N_EDGES + e];
    float dx = pos[c * 3 + 0] - pos[r * 3 + 0];
    float dy = pos[c * 3 + 1] - pos[r * 3 + 1];
    float dz = pos[c * 3 + 2] - pos[r * 3 + 2];
    float dist = sqrtf(dx * dx + dy * dy + dz * dz);
    float inv = 1.0f / (dist + 1e-8f);
    const float INV_DELTA = (float)(TAB_D - 1) / TAB_MAX;
    int p = atomicAdd(&g_cursor[r], 1);
    g_ecol[p] = c;
    g_egeo[p] = make_float4(dx * inv, dy * inv, dz * inv, dist * INV_DELTA);
}

// ---------------- filter table build (single-value NN table) ----------------
#define TAB_SMEM_FLOATS 20736

extern "C" __global__ void __launch_bounds__(512, 1)
table_kernel(const float* __restrict__ fW1, const float* __restrict__ fb1,
             const float* __restrict__ fW2, const float* __restrict__ fb2) {
    extern __shared__ float sm[];
    float* hid = sm;
    float* rbf_s = sm + 8448;
    float* w1_s = sm + 9728;
    float* w2_s = sm + 8448;

    const int tid = threadIdx.x;
    const int layer = blockIdx.y;
    const int g0 = blockIdx.x * 64;
    const float* W1 = fW1 + layer * NRBF * HID;
    const float* b1 = fb1 + layer * HID;
    const float* W2 = fW2 + layer * HID * 3 * HID;
    const float* b2 = fb2 + layer * 3 * HID;
    const float DELTA = TAB_MAX / (float)(TAB_D - 1);

    for (int idx = tid; idx < 64 * NRBF; idx += 512) {
        int e = idx / NRBF, k = idx % NRBF;
        float d = (float)(g0 + e) * DELTA - RBF_STEP * (float)k;
        rbf_s[idx] = expf(-d * d);
    }
    for (int idx = tid; idx < NRBF * HID; idx += 512) w1_s[idx] = W1[idx];
    __syncthreads();

    const int jg = tid & 31;
    const int eg = tid >> 5;
    const int j0 = jg * 4;
    const int el0 = eg * 4;

    float hacc[4][4];
#pragma unroll
    for (int a = 0; a < 4; a++)
#pragma unroll
        for (int b = 0; b < 4; b++) hacc[a][b] = b1[j0 + b];
#pragma unroll
    for (int k = 0; k < NRBF; k++) {
        float r[4];
#pragma unroll
        for (int a = 0; a < 4; a++) r[a] = rbf_s[(el0 + a) * NRBF + k];
        float4 w = *(const float4*)&w1_s[k * HID + j0];
        float wv[4] = {w.x, w.y, w.z, w.w};
#pragma unroll
        for (int a = 0; a < 4; a++)
#pragma unroll
            for (int b = 0; b < 4; b++) hacc[a][b] += r[a] * wv[b];
    }
#pragma unroll
    for (int a = 0; a < 4; a++)
#pragma unroll
        for (int b = 0; b < 4; b++) hid[(el0 + a) * 132 + j0 + b] = silu_f(hacc[a][b]);
    __syncthreads();

    float a_ss[4][4], a_vv[4][4], a_sv[4][4];
#pragma unroll
    for (int a = 0; a < 4; a++)
#pragma unroll
        for (int b = 0; b < 4; b++) { a_ss[a][b] = 0.f; a_vv[a][b] = 0.f; a_sv[a][b] = 0.f; }

    for (int kc = 0; kc < HID; kc += 32) {
        __syncthreads();
        for (int idx = tid; idx < 32 * 384; idx += 512) w2_s[idx] = W2[kc * 384 + idx];
        __syncthreads();
#pragma unroll 8
        for (int kk = 0; kk < 32; kk++) {
            float h[4];
#pragma unroll
            for (int a = 0; a < 4; a++) h[a] = hid[(el0 + a) * 132 + kc + kk];
            float4 wss = *(const float4*)&w2_s[kk * 384 + j0];
            float4 wvv = *(const float4*)&w2_s[kk * 384 + 128 + j0];
            float4 wsv = *(const float4*)&w2_s[kk * 384 + 256 + j0];
            float ss[4] = {wss.x, wss.y, wss.z, wss.w};
            float vv[4] = {wvv.x, wvv.y, wvv.z, wvv.w};
            float sv[4] = {wsv.x, wsv.y, wsv.z, wsv.w};
#pragma unroll
            for (int a = 0; a < 4; a++)
#pragma unroll
                for (int b = 0; b < 4; b++) {
                    a_ss[a][b] += h[a] * ss[b];
                    a_vv[a][b] += h[a] * vv[b];
                    a_sv[a][b] += h[a] * sv[b];
                }
        }
    }

#pragma unroll
    for (int a = 0; a < 4; a++) {
        int gi = g0 + el0 + a;
        __half* Tx = g_htab1 + ((size_t)layer * TAB_D + gi) * 384;
#pragma unroll
        for (int b = 0; b < 4; b++) {
            int ch = j0 + b;
            Tx[ch]       = __float2half(a_ss[a][b] + b2[ch]);
            Tx[128 + ch] = __float2half(a_vv[a][b] + b2[128 + ch]);
            Tx[256 + ch] = __float2half(a_sv[a][b] + b2[256 + ch]);
        }
    }
}

// ---------------- edge message kernel (NN table lookup) ----------------
extern "C" __global__ void __launch_bounds__(256)
msg_kernel(int layer) {
    int r = (blockIdx.x * 256 + threadIdx.x) >> 5;
    int lane = threadIdx.x & 31;
    if (r >= N_ATOMS) return;

    int beg = g_rowptr[r];
    int end = g_rowptr[r + 1];
    int base = r * HID + lane * 4;

    if (beg >= end) {
        uint2 z; z.x = 0u; z.y = 0u;
        *(uint2*)&g_ms[base] = z;
        *(uint2*)&g_vn[base] = z;
        *(uint2*)&g_mvh[0 * NV + base] = z;
        *(uint2*)&g_mvh[1 * NV + base] = z;
        *(uint2*)&g_mvh[2 * NV + base] = z;
        return;
    }

    const bool hasv = (layer != 0);
    const __half* Tl = g_htab1 + (size_t)layer * TAB_D * 384;

    float accS[4] = {0.f, 0.f, 0.f, 0.f};
    float accV[12];
#pragma unroll
    for (int q = 0; q < 12; q++) accV[q] = 0.f;

    int colN = __ldg(&g_ecol[beg]);
    float4 geoN = __ldg(&g_egeo[beg]);
    const __half* TN;
    {
        int i0 = (int)(geoN.w + 0.5f);
        if (i0 > TAB_D - 1) i0 = TAB_D - 1;
        TN = Tl + (size_t)i0 * 384;
    }
    uint2 t0N = __ldg((const uint2*)&TN[lane * 4]);
    uint2 t1N = __ldg((const uint2*)&TN[128 + lane * 4]);
    uint2 t2N = __ldg((const uint2*)&TN[256 + lane * 4]);
    uint2 sN = __ldcg((const uint2*)&g_sh[colN * HID + lane * 4]);
    uint2 v0N, v1N, v2N;
    v0N.x = v0N.y = v1N.x = v1N.y = v2N.x = v2N.y = 0u;
    if (hasv) {
        v0N = __ldcg((const uint2*)&g_vh[0 * NV + colN * HID + lane * 4]);
        v1N = __ldcg((const uint2*)&g_vh[1 * NV + colN * HID + lane * 4]);
        v2N = __ldcg((const uint2*)&g_vh[2 * NV + colN * HID + lane * 4]);
    }

    for (int p = beg; p < end; p++) {
        float4 geo = geoN;
        uint2 t0 = t0N, t1 = t1N, t2 = t2N;
        uint2 sv = sN, v0 = v0N, v1 = v1N, v2 = v2N;

        if (p + 1 < end) {
            int colX = __ldg(&g_ecol[p + 1]);
            geoN = __ldg(&g_egeo[p + 1]);
            int i0 = (int)(geoN.w + 0.5f);
            if (i0 > TAB_D - 1) i0 = TAB_D - 1;
            TN = Tl + (size_t)i0 * 384;
            t0N = __ldg((const uint2*)&TN[lane * 4]);
            t1N = __ldg((const uint2*)&TN[128 + lane * 4]);
            t2N = __ldg((const uint2*)&TN[256 + lane * 4]);
            sN = __ldcg((const uint2*)&g_sh[colX * HID + lane * 4]);
            if (hasv) {
                v0N = __ldcg((const uint2*)&g_vh[0 * NV + colX * HID + lane * 4]);
                v1N = __ldcg((const uint2*)&g_vh[1 * NV + colX * HID + lane * 4]);
                v2N = __ldcg((const uint2*)&g_vh[2 * NV + colX * HID + lane * 4]);
            }
        }

        float4 hssf = h4_to_f4(t0);
        float4 hvvf = h4_to_f4(t1);
        float4 hsvf = h4_to_f4(t2);
        float hss[4] = {hssf.x, hssf.y, hssf.z, hssf.w};
        float hvv[4] = {hvvf.x, hvvf.y, hvvf.z, hvvf.w};
        float hsv[4] = {hsvf.x, hsvf.y, hsvf.z, hsvf.w};

        float4 scf = h4_to_f4(sv);
        float sc[4] = {scf.x, scf.y, scf.z, scf.w};
        float vc0[4], vc1[4], vc2[4];
        if (hasv) {
            float4 a0 = h4_to_f4(v0);
            float4 a1 = h4_to_f4(v1);
            float4 a2 = h4_to_f4(v2);
            vc0[0] = a0.x; vc0[1] = a0.y; vc0[2] = a0.z; vc0[3] = a0.w;
            vc1[0] = a1.x; vc1[1] = a1.y; vc1[2] = a1.z; vc1[3] = a1.w;
            vc2[0] = a2.x; vc2[1] = a2.y; vc2[2] = a2.z; vc2[3] = a2.w;
        }

#pragma unroll
        for (int c = 0; c < 4; c++) {
            accS[c] += hss[c] * sc[c];
            float cc = hsv[c] * sc[c];
            if (hasv) {
                accV[c]     += hvv[c] * vc0[c] + cc * geo.x;
                accV[4 + c] += hvv[c] * vc1[c] + cc * geo.y;
                accV[8 + c] += hvv[c] * vc2[c] + cc * geo.z;
            } else {
                accV[c]     += cc * geo.x;
                accV[4 + c] += cc * geo.y;
                accV[8 + c] += cc * geo.z;
            }
        }
    }

    *(uint2*)&g_ms[base] = f4_to_h4(accS[0], accS[1], accS[2], accS[3]);
    float vn[4];
#pragma unroll
    for (int c = 0; c < 4; c++)
        vn[c] = sqrtf(accV[c] * accV[c] + accV[4 + c] * accV[4 + c] + accV[8 + c] * accV[8 + c]);
    *(uint2*)&g_vn[base] = f4_to_h4(vn[0], vn[1], vn[2], vn[3]);
    *(uint2*)&g_mvh[0 * NV + base] = f4_to_h4(accV[0], accV[1], accV[2], accV[3]);
    *(uint2*)&g_mvh[1 * NV + base] = f4_to_h4(accV[4], accV[5], accV[6], accV[7]);
    *(uint2*)&g_mvh[2 * NV + base] = f4_to_h4(accV[8], accV[9], accV[10], accV[11]);
}

// ---------------- node update kernel (tf32 mma.sync; fused pooling on last layer) ----------------
#define NT 64
#define XS_STRIDE 76
#define WC_STRIDE 132
#define NODE_SMEM_FLOATS 23040

extern "C" __global__ void __launch_bounds__(256, 2)
node_kernel(int layer, const int* __restrict__ batch,
            const float* __restrict__ uW1, const float* __restrict__ ub1,
            const float* __restrict__ uW2, const float* __restrict__ ub2) {
    extern __shared__ float sm[];
    float* xs_t = sm;
    float* wc   = sm + 4864;
    float* ts_t = sm + 13312;
    __half* alpha_s = (__half*)sm;

    const int tid = threadIdx.x;
    const int n0 = blockIdx.x * NT;
    const float* W1 = uW1 + layer * 384 * HID;
    const float* b1 = ub1 + layer * HID;
    const float* W2 = uW2 + layer * HID * 384;
    const float* b2 = ub2 + layer * 384;

    const int w = tid >> 5;
    const int lane = tid & 31;
    const int gid = lane >> 2;
    const int tig = lane & 3;
    const int wn2 = w >> 2;
    const int wcq = w & 3;
    const int nbase = 32 * wn2 + gid;
    const int cbase = 32 * wcq + gid;

    const int snode = tid & 63;
    const int sq = (tid >> 6) << 2;
    const int sgn = n0 + snode;
    const bool svalid = (sgn < N_ATOMS);

    float4 wreg[8];
#pragma unroll
    for (int q = 0; q < 8; q++) {
        int idx = q * 256 + tid;
        int k = idx >> 5, c4 = idx & 31;
        wreg[q] = *(const float4*)&W1[k * HID + c4 * 4];
    }

    float4 xpre[4];
    {
        const float* sp = g_s + (size_t)sgn * HID;
#pragma unroll
        for (int q = 0; q < 4; q++)
            xpre[q] = svalid ? *(const float4*)&sp[sq + 16 * q]
                             : make_float4(0.f, 0.f, 0.f, 0.f);
    }

    // ---- stage 1: T = silu(X @ W1 + b1) ----
    float c1r[2][4][4];
#pragma unroll
    for (int nt = 0; nt < 4; nt++) {
        int cl = 32 * wcq + 8 * nt + 2 * tig;
        float bb0 = b1[cl], bb1 = b1[cl + 1];
#pragma unroll
        for (int mt = 0; mt < 2; mt++) {
            c1r[mt][nt][0] = bb0; c1r[mt][nt][1] = bb1;
            c1r[mt][nt][2] = bb0; c1r[mt][nt][3] = bb1;
        }
    }

    for (int kc = 0; kc < 384; kc += 64) {
        __syncthreads();
#pragma unroll
        for (int q = 0; q < 8; q++) {
            int idx = q * 256 + tid;
            int k = idx >> 5, c4 = idx & 31;
            *(float4*)&wc[k * WC_STRIDE + c4 * 4] =
                make_float4(tf32f(wreg[q].x), tf32f(wreg[q].y),
                            tf32f(wreg[q].z), tf32f(wreg[q].w));
        }
#pragma unroll
        for (int q = 0; q < 4; q++) {
            int kl = sq + 16 * q;
            xs_t[(kl + 0) * XS_STRIDE + snode] = tf32f(xpre[q].x);
            xs_t[(kl + 1) * XS_STRIDE + snode] = tf32f(xpre[q].y);
            xs_t[(kl + 2) * XS_STRIDE + snode] = tf32f(xpre[q].z);
            xs_t[(kl + 3) * XS_STRIDE + snode] = tf32f(xpre[q].w);
        }
        __syncthreads();
        if (kc + 64 < 384) {
            int nkc = kc + 64;
#pragma unroll
            for (int q = 0; q < 8; q++) {
                int idx = q * 256 + tid;
                int k = idx >> 5, c4 = idx & 31;
                wreg[q] = *(const float4*)&W1[(nkc + k) * HID + c4 * 4];
            }
            if (nkc < 128) {
                const float* sp = g_s + (size_t)sgn * HID + nkc;
#pragma unroll
                for (int q = 0; q < 4; q++)
                    xpre[q] = svalid ? *(const float4*)&sp[sq + 16 * q]
                                     : make_float4(0.f, 0.f, 0.f, 0.f);
            } else {
                const __half* hp = ((nkc < 256) ? g_ms : g_vn) + (size_t)sgn * HID + (nkc & 127);
#pragma unroll
                for (int q = 0; q < 4; q++)
                    xpre[q] = svalid ? h4_to_f4(*(const uint2*)&hp[sq + 16 * q])
                                     : make_float4(0.f, 0.f, 0.f, 0.f);
            }
        } else {
#pragma unroll
            for (int q = 0; q < 8; q++) {
                int idx = q * 256 + tid;
                int k = idx >> 5, c4 = idx & 31;
                wreg[q] = *(const float4*)&W2[k * 384 + c4 * 4];
            }
        }
#pragma unroll
        for (int kk8 = 0; kk8 < 8; kk8++) {
            int kb = kk8 * 8;
            const float* xr0 = &xs_t[(kb + tig) * XS_STRIDE];
            const float* xr1 = &xs_t[(kb + tig + 4) * XS_STRIDE];
            uint a[2][4];
#pragma unroll
            for (int mt = 0; mt < 2; mt++) {
                int nb = nbase + 16 * mt;
                a[mt][0] = __float_as_uint(xr0[nb]);
                a[mt][1] = __float_as_uint(xr0[nb + 8]);
                a[mt][2] = __float_as_uint(xr1[nb]);
                a[mt][3] = __float_as_uint(xr1[nb + 8]);
            }
            const float* wr0 = &wc[(kb + tig) * WC_STRIDE];
            const float* wr1 = &wc[(kb + tig + 4) * WC_STRIDE];
#pragma unroll
            for (int nt = 0; nt < 4; nt++) {
                uint b0 = __float_as_uint(wr0[cbase + 8 * nt]);
                uint b1u = __float_as_uint(wr1[cbase + 8 * nt]);
                mma_tf32(c1r[0][nt], a[0][0], a[0][1], a[0][2], a[0][3], b0, b1u);
                mma_tf32(c1r[1][nt], a[1][0], a[1][1], a[1][2], a[1][3], b0, b1u);
            }
        }
    }

#pragma unroll
    for (int mt = 0; mt < 2; mt++) {
        int lr = 32 * wn2 + 16 * mt + gid;
#pragma unroll
        for (int nt = 0; nt < 4; nt++) {
            int cl = 32 * wcq + 8 * nt + 2 * tig;
            ts_t[(cl + 0) * XS_STRIDE + lr]     = tf32f(silu_f(c1r[mt][nt][0]));
            ts_t[(cl + 1) * XS_STRIDE + lr]     = tf32f(silu_f(c1r[mt][nt][1]));
            ts_t[(cl + 0) * XS_STRIDE + lr + 8] = tf32f(silu_f(c1r[mt][nt][2]));
            ts_t[(cl + 1) * XS_STRIDE + lr + 8] = tf32f(silu_f(c1r[mt][nt][3]));
        }
    }

    // ---- stage 2: U = T @ W2 + b2 ----
    float u2r[2][4][4];
    for (int c = 0; c < 6; c++) {
        int jb = c >> 1;
        int kc2 = (c & 1) * 64;
        if (kc2 == 0) {
#pragma unroll
            for (int mt = 0; mt < 2; mt++)
#pragma unroll
                for (int nt = 0; nt < 4; nt++)
#pragma unroll
                    for (int x = 0; x < 4; x++) u2r[mt][nt][x] = 0.f;
        }
        __syncthreads();
#pragma unroll
        for (int q = 0; q < 8; q++) {
            int idx = q * 256 + tid;
            int k = idx >> 5, c4 = idx & 31;
            *(float4*)&wc[k * WC_STRIDE + c4 * 4] =
                make_float4(tf32f(wreg[q].x), tf32f(wreg[q].y),
                            tf32f(wreg[q].z), tf32f(wreg[q].w));
        }
        __syncthreads();
        if (c < 5) {
            int cn = c + 1;
            int jbn = cn >> 1;
            int kc2n = (cn & 1) * 64;
#pragma unroll
            for (int q = 0; q < 8; q++) {
                int idx = q * 256 + tid;
                int k = idx >> 5, c4 = idx & 31;
                wreg[q] = *(const float4*)&W2[(kc2n + k) * 384 + jbn * 128 + c4 * 4];
            }
        }
#pragma unroll
        for (int kk8 = 0; kk8 < 8; kk8++) {
            int kb = kk8 * 8;
            const float* tr0 = &ts_t[(kc2 + kb + tig) * XS_STRIDE];
            const float* tr1 = &ts_t[(kc2 + kb + tig + 4) * XS_STRIDE];
            uint a[2][4];
#pragma unroll
            for (int mt = 0; mt < 2; mt++) {
                int nb = nbase + 16 * mt;
                a[mt][0] = __float_as_uint(tr0[nb]);
                a[mt][1] = __float_as_uint(tr0[nb + 8]);
                a[mt][2] = __float_as_uint(tr1[nb]);
                a[mt][3] = __float_as_uint(tr1[nb + 8]);
            }
            const float* wr0 = &wc[(kb + tig) * WC_STRIDE];
            const float* wr1 = &wc[(kb + tig + 4) * WC_STRIDE];
#pragma unroll
            for (int nt = 0; nt < 4; nt++) {
                uint b0 = __float_as_uint(wr0[cbase + 8 * nt]);
                uint b1u = __float_as_uint(wr1[cbase + 8 * nt]);
                mma_tf32(u2r[0][nt], a[0][0], a[0][1], a[0][2], a[0][3], b0, b1u);
                mma_tf32(u2r[1][nt], a[1][0], a[1][1], a[1][2], a[1][3], b0, b1u);
            }
        }

        if (kc2 == 64) {
#pragma unroll
            for (int mt = 0; mt < 2; mt++) {
#pragma unroll
                for (int rs = 0; rs < 2; rs++) {
                    int lr = 32 * wn2 + 16 * mt + gid + rs * 8;
                    int gn = n0 + lr;
                    if (gn >= N_ATOMS) continue;
#pragma unroll
                    for (int nt = 0; nt < 4; nt++) {
                        int j = 32 * wcq + 8 * nt + 2 * tig;
                        float u0 = u2r[mt][nt][rs * 2 + 0] + b2[jb * 128 + j];
                        float u1 = u2r[mt][nt][rs * 2 + 1] + b2[jb * 128 + j + 1];
                        if (jb == 0) {
                            float2* sp = (float2*)&g_s[gn * HID + j];
                            float2 s = *sp;
                            s.x += u0; s.y += u1;
                            *sp = s;
                            *(__half2*)&g_sh[gn * HID + j] = __floats2half2_rn(s.x, s.y);
                            if (layer == NLAYERS - 1) {
                                int m = batch[gn];
                                atomicAdd(&g_hmol[m * HID + j], s.x);
                                atomicAdd(&g_hmol[m * HID + j + 1], s.y);
                            }
                        } else if (jb == 1) {
                            *(__half2*)&alpha_s[lr * HID + j] = __floats2half2_rn(u0, u1);
                        } else {
                            float2 al = __half22float2(*(__half2*)&alpha_s[lr * HID + j]);
#pragma unroll
                            for (int d = 0; d < 3; d++) {
                                float2 mv = __half22float2(*(__half2*)&g_mvh[d * NV + gn * HID + j]);
                                float2 vo = make_float2(0.f, 0.f);
                                if (layer != 0)
                                    vo = __half22float2(*(__half2*)&g_vh[d * NV + gn * HID + j]);
                                float nx = al.x * vo.x + u0 * mv.x;
                                float ny = al.y * vo.y + u1 * mv.y;
                                *(__half2*)&g_vh[d * NV + gn * HID + j] = __floats2half2_rn(nx, ny);
                            }
                        }
                    }
                }
            }
        }
    }
}

// ---------------- heads ----------------
__global__ void head_kernel(const float* __restrict__ lW1, const float* __restrict__ lb1,
                            const float* __restrict__ lW2, const float* __restrict__ lb2,
                            const float* __restrict__ pW1, const float* __restrict__ pb1,
                            const float* __restrict__ pW2, const float* __restrict__ pb2,
                            float* __restrict__ out) {
    __shared__ float hm[HID];
    __shared__ float tt[HID];
    __shared__ float red[HID];
    int m = blockIdx.x;
    int j = threadIdx.x;
    float cnt = g_cnt[m];
    hm[j] = g_hmol[m * HID + j] / cnt;
    __syncthreads();

    float acc = lb1[j];
    for (int k = 0; k < HID; k++) acc += hm[k] * lW1[k * HID + j];
    tt[j] = silu_f(acc);
    __syncthreads();
    red[j] = tt[j] * lW2[j];
    __syncthreads();
    for (int s = 64; s > 0; s >>= 1) {
        if (j < s) red[j] += red[j + s];
        __syncthreads();
    }
    if (j == 0) out[m] = red[0] + lb2[0];
    __syncthreads();

    acc = pb1[j];
    for (int k = 0; k < HID; k++) acc += hm[k] * pW1[k * HID + j];
    tt[j] = silu_f(acc);
    __syncthreads();
    red[j] = tt[j] * pW2[j];
    __syncthreads();
    for (int s = 64; s > 0; s >>= 1) {
        if (j < s) red[j] += red[j + s];
        __syncthreads();
    }
    if (j == 0) {
        float x = red[0] + pb2[0];
        out[N_MOLS + m] = 1.0f / (1.0f + expf(-x));
    }
}

// ---------------- launch ----------------
extern "C" void kernel_launch(void* const* d_in, const int* in_sizes, int n_in,
                              void* d_out, int out_size) {
    const int* z = (const int*)d_in[0];
    const float* pos = (const float*)d_in[1];
    const int* ei = (const int*)d_in[2];
    const int* batch = (const int*)d_in[3];
    const float* emb = (const float*)d_in[4];
    const float* fW1 = (const float*)d_in[5];
    const float* fb1 = (const float*)d_in[6];
    const float* fW2 = (const float*)d_in[7];
    const float* fb2 = (const float*)d_in[8];
    const float* uW1 = (const float*)d_in[9];
    const float* ub1 = (const float*)d_in[10];
    const float* uW2 = (const float*)d_in[11];
    const float* ub2 = (const float*)d_in[12];
    const float* lW1 = (const float*)d_in[13];
    const float* lb1 = (const float*)d_in[14];
    const float* lW2 = (const float*)d_in[15];
    const float* lb2 = (const float*)d_in[16];
    const float* pW1 = (const float*)d_in[17];
    const float* pb1 = (const float*)d_in[18];
    const float* pW2 = (const float*)d_in[19];
    const float* pb2 = (const float*)d_in[20];
    float* out = (float*)d_out;

    cudaFuncSetAttribute(table_kernel, cudaFuncAttributeMaxDynamicSharedMemorySize,
                         TAB_SMEM_FLOATS * 4);
    cudaFuncSetAttribute(node_kernel, cudaFuncAttributeMaxDynamicSharedMemorySize,
                         NODE_SMEM_FLOATS * 4);

    init_kernel<<<(NV + 255) / 256, 256>>>(z, emb);

    const int scan_blocks = (N_ATOMS + SCAN_B - 1) / SCAN_B;
    hist_kernel<<<(N_EDGES + 255) / 256, 256>>>(ei);
    scan1_kernel<<<scan_blocks, SCAN_B>>>();
    scan2_kernel<<<1, 128>>>(scan_blocks);
    scan3_kernel<<<(N_ATOMS + 255) / 256, 256>>>(batch);
    scatter_kernel<<<(N_EDGES + 255) / 256, 256>>>(ei, pos);

    table_kernel<<<dim3(TAB_D / 64, NLAYERS), 512, TAB_SMEM_FLOATS * 4>>>(fW1, fb1, fW2, fb2);

    const int msg_blocks = (N_ATOMS * 32 + 255) / 256;
    const int node_blocks = (N_ATOMS + NT - 1) / NT;
    for (int layer = 0; layer < NLAYERS; layer++) {
        msg_kernel<<<msg_blocks, 256>>>(layer);
        node_kernel<<<node_blocks, 256, NODE_SMEM_FLOATS * 4>>>(layer, batch, uW1, ub1, uW2, ub2);
    }

    head_kernel<<<N_MOLS, HID>>>(lW1, lb1, lW2, lb2, pW1, pb1, pW2, pb2, out);
}